// round 3
// baseline (speedup 1.0000x reference)
#include <cuda_runtime.h>

#define BATCH 8
#define CH    128
#define HW    4096
#define NG    32
#define CPG   4
#define GRP_ELEMS (CPG*HW)

__device__ float g_xn  [BATCH*CH*HW];
__device__ float g_qkv [BATCH*3*CH*HW];
__device__ float g_attn[BATCH*CH*HW];

// packed f32x2 helpers
__device__ __forceinline__ unsigned long long pk2(float lo, float hi) {
    unsigned long long r;
    asm("mov.b64 %0, {%1,%2};" : "=l"(r) : "f"(lo), "f"(hi));
    return r;
}
__device__ __forceinline__ void upk2(unsigned long long v, float& lo, float& hi) {
    asm("mov.b64 {%0,%1}, %2;" : "=f"(lo), "=f"(hi) : "l"(v));
}
__device__ __forceinline__ void fma2(unsigned long long& d, unsigned long long a, unsigned long long b) {
    asm("fma.rn.f32x2 %0, %1, %2, %0;" : "+l"(d) : "l"(a), "l"(b));
}
__device__ __forceinline__ void mul2(unsigned long long& d, unsigned long long a) {
    asm("mul.rn.f32x2 %0, %0, %1;" : "+l"(d) : "l"(a));
}

// ============================ GroupNorm ============================
__global__ void __launch_bounds__(256) gn_kernel(const float* __restrict__ x,
                                                 const float* __restrict__ gamma,
                                                 const float* __restrict__ beta) {
    const int bg  = blockIdx.x;          // b*32+g
    const int tid = threadIdx.x;
    const float* src = x    + (size_t)bg * GRP_ELEMS;
    float*       dst = g_xn + (size_t)bg * GRP_ELEMS;

    float s = 0.f, ss = 0.f;
    const float4* src4 = (const float4*)src;
    for (int i = tid; i < GRP_ELEMS/4; i += 256) {
        float4 v = src4[i];
        s  += v.x + v.y + v.z + v.w;
        ss += v.x*v.x + v.y*v.y + v.z*v.z + v.w*v.w;
    }
    __shared__ float rs[256], rss[256];
    rs[tid] = s; rss[tid] = ss;
    __syncthreads();
    for (int o = 128; o > 0; o >>= 1) {
        if (tid < o) { rs[tid] += rs[tid+o]; rss[tid] += rss[tid+o]; }
        __syncthreads();
    }
    const float mean = rs[0]  * (1.f/GRP_ELEMS);
    const float var  = rss[0] * (1.f/GRP_ELEMS) - mean*mean;
    const float rstd = rsqrtf(var + 1e-5f);
    const int c0 = (bg % NG) * CPG;

    float4* dst4 = (float4*)dst;
    for (int i = tid; i < GRP_ELEMS/4; i += 256) {
        const int c = c0 + (i*4)/HW;     // 4 lanes share channel (HW%4==0)
        const float ga = gamma[c], be = beta[c];
        float4 v = src4[i];
        v.x = (v.x-mean)*rstd*ga + be;
        v.y = (v.y-mean)*rstd*ga + be;
        v.z = (v.z-mean)*rstd*ga + be;
        v.w = (v.w-mean)*rstd*ga + be;
        dst4[i] = v;
    }
}

// ============================ QKV GEMM =============================
// out[o,p] = sum_c W[o,c]*xn[b,c,p] + bias[o]; 128x128 tile, K=128 resident
#define SA 132
#define SB 132
#define SM_GEMM (2*128*132*sizeof(float))

__global__ void __launch_bounds__(256) qkv_kernel(const float* __restrict__ W,
                                                  const float* __restrict__ bias) {
    const int b  = blockIdx.z;
    const int o0 = blockIdx.y * 128;
    const int p0 = blockIdx.x * 128;
    extern __shared__ float sm[];
    float* As = sm;              // [c][o]
    float* Bs = sm + 128*SA;     // [c][p]
    const int tid = threadIdx.x;

    for (int idx = tid*4; idx < 128*128; idx += 1024) {
        const int o = idx >> 7, c = idx & 127;
        float4 w = *(const float4*)&W[(size_t)(o0+o)*CH + c];
        As[(c+0)*SA + o] = w.x; As[(c+1)*SA + o] = w.y;
        As[(c+2)*SA + o] = w.z; As[(c+3)*SA + o] = w.w;
    }
    const float* xb = g_xn + (size_t)b*CH*HW;
    for (int idx = tid*4; idx < 128*128; idx += 1024) {
        const int c = idx >> 7, p = idx & 127;
        *(float4*)&Bs[c*SB + p] = *(const float4*)&xb[(size_t)c*HW + p0 + p];
    }
    __syncthreads();

    const int tx = tid & 15, ty = tid >> 4;
    unsigned long long acc[8][4];
#pragma unroll
    for (int i = 0; i < 8; i++)
#pragma unroll
        for (int j = 0; j < 4; j++) acc[i][j] = 0ull;

#pragma unroll 4
    for (int c = 0; c < 128; c++) {
        float4 a0 = *(const float4*)&As[c*SA + ty*8];
        float4 a1 = *(const float4*)&As[c*SA + ty*8 + 4];
        longlong2 kb0 = *(const longlong2*)&Bs[c*SB + tx*8];
        longlong2 kb1 = *(const longlong2*)&Bs[c*SB + tx*8 + 4];
        const unsigned long long b0=(unsigned long long)kb0.x, b1=(unsigned long long)kb0.y;
        const unsigned long long b2=(unsigned long long)kb1.x, b3=(unsigned long long)kb1.y;
        const float av[8] = {a0.x,a0.y,a0.z,a0.w,a1.x,a1.y,a1.z,a1.w};
#pragma unroll
        for (int i = 0; i < 8; i++) {
            unsigned long long aa = pk2(av[i], av[i]);
            fma2(acc[i][0], aa, b0); fma2(acc[i][1], aa, b1);
            fma2(acc[i][2], aa, b2); fma2(acc[i][3], aa, b3);
        }
    }

    float* qb = g_qkv + (size_t)b*3*CH*HW;
#pragma unroll
    for (int i = 0; i < 8; i++) {
        const int o = o0 + ty*8 + i;
        const float bo = bias[o];
#pragma unroll
        for (int j2 = 0; j2 < 4; j2++) {
            float lo, hi; upk2(acc[i][j2], lo, hi);
            float2 v; v.x = lo + bo; v.y = hi + bo;
            *(float2*)&qb[(size_t)o*HW + p0 + tx*8 + 2*j2] = v;
        }
    }
}

// ========================= Flash attention =========================
#define SQ   132
#define SKst 132
#define SVst 130
#define SP   130
#define SM_FLASH ((2*128*132 + 128*130)*sizeof(float))

__global__ void __launch_bounds__(256) flash_kernel() {
    extern __shared__ float sm[];
    float* Qs = sm;                  // [c][n] 128*132
    float* Ks = sm + 128*132;        // [c][m] (reused as Vs [m][c])
    float* Vs = Ks;
    float* Ps = sm + 2*128*132;      // [n][m] 128*130

    const int b   = blockIdx.y;
    const int n0  = blockIdx.x * 128;
    const int tid = threadIdx.x;
    const int tx  = tid & 15, ty = tid >> 4;
    const float scale = 0.08838834764831845f;   // 1/sqrt(128)

    const float* qg = g_qkv + (size_t)b*3*CH*HW;

    for (int idx = tid*4; idx < 128*128; idx += 1024) {
        const int c = idx >> 7, n = idx & 127;
        float4 v = *(const float4*)&qg[(size_t)c*HW + n0 + n];
        v.x *= scale; v.y *= scale; v.z *= scale; v.w *= scale;
        *(float4*)&Qs[c*SQ + n] = v;
    }

    float rmax[8], rsum[8];
    unsigned long long o2[8][4];
#pragma unroll
    for (int i = 0; i < 8; i++) {
        rmax[i] = -1e30f; rsum[i] = 0.f;
#pragma unroll
        for (int j = 0; j < 4; j++) o2[i][j] = 0ull;
    }

    for (int kt = 0; kt < 32; kt++) {
        const int m0 = kt * 128;
        for (int idx = tid*4; idx < 128*128; idx += 1024) {
            const int c = idx >> 7, m = idx & 127;
            *(float4*)&Ks[c*SKst + m] =
                *(const float4*)&qg[(size_t)(128+c)*HW + m0 + m];
        }
        __syncthreads();

        // S = Q^T K
        unsigned long long s2[8][4];
#pragma unroll
        for (int i = 0; i < 8; i++)
#pragma unroll
            for (int j = 0; j < 4; j++) s2[i][j] = 0ull;

#pragma unroll 4
        for (int c = 0; c < 128; c++) {
            float4 a0 = *(const float4*)&Qs[c*SQ + ty*8];
            float4 a1 = *(const float4*)&Qs[c*SQ + ty*8 + 4];
            longlong2 kb0 = *(const longlong2*)&Ks[c*SKst + tx*8];
            longlong2 kb1 = *(const longlong2*)&Ks[c*SKst + tx*8 + 4];
            const unsigned long long b0=(unsigned long long)kb0.x, b1=(unsigned long long)kb0.y;
            const unsigned long long b2=(unsigned long long)kb1.x, b3=(unsigned long long)kb1.y;
            const float av[8] = {a0.x,a0.y,a0.z,a0.w,a1.x,a1.y,a1.z,a1.w};
#pragma unroll
            for (int i = 0; i < 8; i++) {
                unsigned long long aa = pk2(av[i], av[i]);
                fma2(s2[i][0], aa, b0); fma2(s2[i][1], aa, b1);
                fma2(s2[i][2], aa, b2); fma2(s2[i][3], aa, b3);
            }
        }
        __syncthreads();   // Ks reads done before V overwrites

        // online softmax; row stats across 16 tx-lanes (shfl group = 16)
#pragma unroll
        for (int i = 0; i < 8; i++) {
            float p[8];
            upk2(s2[i][0], p[0], p[1]); upk2(s2[i][1], p[2], p[3]);
            upk2(s2[i][2], p[4], p[5]); upk2(s2[i][3], p[6], p[7]);
            float tm = p[0];
#pragma unroll
            for (int j = 1; j < 8; j++) tm = fmaxf(tm, p[j]);
#pragma unroll
            for (int off = 8; off > 0; off >>= 1)
                tm = fmaxf(tm, __shfl_xor_sync(0xffffffffu, tm, off));
            const float mnew = fmaxf(rmax[i], tm);
            const float corr = __expf(rmax[i] - mnew);
            rmax[i] = mnew;
            float rsacc = 0.f;
#pragma unroll
            for (int j = 0; j < 8; j++) { p[j] = __expf(p[j] - mnew); rsacc += p[j]; }
#pragma unroll
            for (int off = 8; off > 0; off >>= 1)
                rsacc += __shfl_xor_sync(0xffffffffu, rsacc, off);
            rsum[i] = rsum[i]*corr + rsacc;
            const unsigned long long cc = pk2(corr, corr);
#pragma unroll
            for (int j2 = 0; j2 < 4; j2++) {
                mul2(o2[i][j2], cc);
                float2 pv; pv.x = p[2*j2]; pv.y = p[2*j2+1];
                *(float2*)&Ps[(ty*8+i)*SP + tx*8 + 2*j2] = pv;
            }
        }

        // stage V transposed [m][c] into Ks buffer
        for (int idx = tid*4; idx < 128*128; idx += 1024) {
            const int c = idx >> 7, m = idx & 127;
            float4 v = *(const float4*)&qg[(size_t)(256+c)*HW + m0 + m];
            Vs[(m+0)*SVst + c] = v.x; Vs[(m+1)*SVst + c] = v.y;
            Vs[(m+2)*SVst + c] = v.z; Vs[(m+3)*SVst + c] = v.w;
        }
        __syncthreads();

        // O += P V
#pragma unroll 2
        for (int m = 0; m < 128; m += 2) {
            unsigned long long vv0[4], vv1[4];
#pragma unroll
            for (int j2 = 0; j2 < 4; j2++) {
                vv0[j2] = *(const unsigned long long*)&Vs[(m  )*SVst + tx*8 + 2*j2];
                vv1[j2] = *(const unsigned long long*)&Vs[(m+1)*SVst + tx*8 + 2*j2];
            }
#pragma unroll
            for (int i = 0; i < 8; i++) {
                float2 pp = *(const float2*)&Ps[(ty*8+i)*SP + m];
                unsigned long long pa = pk2(pp.x, pp.x);
                unsigned long long pb = pk2(pp.y, pp.y);
#pragma unroll
                for (int j2 = 0; j2 < 4; j2++) {
                    fma2(o2[i][j2], pa, vv0[j2]);
                    fma2(o2[i][j2], pb, vv1[j2]);
                }
            }
        }
        __syncthreads();   // PV done before next K stage
    }

    // epilogue: normalize + transpose to [c][n] via smem
    float* Ts = Qs;
#pragma unroll
    for (int i = 0; i < 8; i++) {
        const float inv = 1.0f / rsum[i];
#pragma unroll
        for (int j2 = 0; j2 < 4; j2++) {
            float lo, hi; upk2(o2[i][j2], lo, hi);
            Ts[(tx*8 + 2*j2    )*132 + ty*8 + i] = lo * inv;
            Ts[(tx*8 + 2*j2 + 1)*132 + ty*8 + i] = hi * inv;
        }
    }
    __syncthreads();
    float* ab = g_attn + (size_t)b*CH*HW;
    for (int idx = tid*4; idx < 128*128; idx += 1024) {
        const int c = idx >> 7, n = idx & 127;
        *(float4*)&ab[(size_t)c*HW + n0 + n] = *(const float4*)&Ts[c*132 + n];
    }
}

// ================== Output GEMM + bias + residual ==================
__global__ void __launch_bounds__(256) out_kernel(const float* __restrict__ W,
                                                  const float* __restrict__ bias,
                                                  const float* __restrict__ x,
                                                  float* __restrict__ out) {
    const int b  = blockIdx.y;
    const int p0 = blockIdx.x * 128;
    extern __shared__ float sm[];
    float* As = sm;
    float* Bs = sm + 128*SA;
    const int tid = threadIdx.x;

    for (int idx = tid*4; idx < 128*128; idx += 1024) {
        const int o = idx >> 7, c = idx & 127;
        float4 w = *(const float4*)&W[(size_t)o*CH + c];
        As[(c+0)*SA + o] = w.x; As[(c+1)*SA + o] = w.y;
        As[(c+2)*SA + o] = w.z; As[(c+3)*SA + o] = w.w;
    }
    const float* ab = g_attn + (size_t)b*CH*HW;
    for (int idx = tid*4; idx < 128*128; idx += 1024) {
        const int c = idx >> 7, p = idx & 127;
        *(float4*)&Bs[c*SB + p] = *(const float4*)&ab[(size_t)c*HW + p0 + p];
    }
    __syncthreads();

    const int tx = tid & 15, ty = tid >> 4;
    unsigned long long acc[8][4];
#pragma unroll
    for (int i = 0; i < 8; i++)
#pragma unroll
        for (int j = 0; j < 4; j++) acc[i][j] = 0ull;

#pragma unroll 4
    for (int c = 0; c < 128; c++) {
        float4 a0 = *(const float4*)&As[c*SA + ty*8];
        float4 a1 = *(const float4*)&As[c*SA + ty*8 + 4];
        longlong2 kb0 = *(const longlong2*)&Bs[c*SB + tx*8];
        longlong2 kb1 = *(const longlong2*)&Bs[c*SB + tx*8 + 4];
        const unsigned long long b0=(unsigned long long)kb0.x, b1=(unsigned long long)kb0.y;
        const unsigned long long b2=(unsigned long long)kb1.x, b3=(unsigned long long)kb1.y;
        const float av[8] = {a0.x,a0.y,a0.z,a0.w,a1.x,a1.y,a1.z,a1.w};
#pragma unroll
        for (int i = 0; i < 8; i++) {
            unsigned long long aa = pk2(av[i], av[i]);
            fma2(acc[i][0], aa, b0); fma2(acc[i][1], aa, b1);
            fma2(acc[i][2], aa, b2); fma2(acc[i][3], aa, b3);
        }
    }

#pragma unroll
    for (int i = 0; i < 8; i++) {
        const int o = ty*8 + i;
        const float bo = bias[o];
        const size_t row = ((size_t)b*CH + o)*HW + p0;
#pragma unroll
        for (int j2 = 0; j2 < 4; j2++) {
            float lo, hi; upk2(acc[i][j2], lo, hi);
            float2 xr = *(const float2*)&x[row + tx*8 + 2*j2];
            float2 v; v.x = lo + bo + xr.x; v.y = hi + bo + xr.y;
            *(float2*)&out[row + tx*8 + 2*j2] = v;
        }
    }
}

// ===================================================================
extern "C" void kernel_launch(void* const* d_in, const int* in_sizes, int n_in,
                              void* d_out, int out_size) {
    const float* x     = (const float*)d_in[0];
    const float* gamma = (const float*)d_in[1];
    const float* beta  = (const float*)d_in[2];
    const float* w_qkv = (const float*)d_in[3];
    const float* b_qkv = (const float*)d_in[4];
    const float* w_out = (const float*)d_in[5];
    const float* b_out = (const float*)d_in[6];
    float*       out   = (float*)d_out;

    static bool attr_set = false;
    if (!attr_set) {
        cudaFuncSetAttribute(qkv_kernel,   cudaFuncAttributeMaxDynamicSharedMemorySize, (int)SM_GEMM);
        cudaFuncSetAttribute(flash_kernel, cudaFuncAttributeMaxDynamicSharedMemorySize, (int)SM_FLASH);
        cudaFuncSetAttribute(out_kernel,   cudaFuncAttributeMaxDynamicSharedMemorySize, (int)SM_GEMM);
        attr_set = true;
    }

    gn_kernel<<<BATCH*NG, 256>>>(x, gamma, beta);

    dim3 gq(HW/128, 3, BATCH);                 // 32 x 3 x 8
    qkv_kernel<<<gq, 256, SM_GEMM>>>(w_qkv, b_qkv);

    dim3 gf(HW/128, BATCH);                    // 32 x 8
    flash_kernel<<<gf, 256, SM_FLASH>>>();

    dim3 go(HW/128, BATCH);                    // 32 x 8
    out_kernel<<<go, 256, SM_GEMM>>>(w_out, b_out, x, out);
}

// round 5
// speedup vs baseline: 5.0692x; 5.0692x over previous
#include <cuda_runtime.h>
#include <cuda_bf16.h>
#include <cstdint>

#define BATCH 8
#define CH    128
#define HW    4096
#define NG    32
#define CPG   4
#define GRP_ELEMS (CPG*HW)
#define SCALE_Q 0.08838834764831845f   // 1/sqrt(128)

__device__ float         g_xn  [BATCH*CH*HW];
__device__ float         g_attn[BATCH*CH*HW];
__device__ __nv_bfloat16 g_q   [BATCH*HW*CH];   // [b][n][c], scale folded
__device__ __nv_bfloat16 g_k   [BATCH*HW*CH];   // [b][m][c]
__device__ __nv_bfloat16 g_v   [BATCH*CH*HW];   // [b][c][m]

// ---------------- packed f32x2 helpers ----------------
__device__ __forceinline__ unsigned long long pk2(float lo, float hi) {
    unsigned long long r;
    asm("mov.b64 %0, {%1,%2};" : "=l"(r) : "f"(lo), "f"(hi));
    return r;
}
__device__ __forceinline__ void upk2(unsigned long long v, float& lo, float& hi) {
    asm("mov.b64 {%0,%1}, %2;" : "=f"(lo), "=f"(hi) : "l"(v));
}
__device__ __forceinline__ void fma2(unsigned long long& d, unsigned long long a, unsigned long long b) {
    asm("fma.rn.f32x2 %0, %1, %2, %0;" : "+l"(d) : "l"(a), "l"(b));
}

// ---------------- mma.sync / ldmatrix / cp.async helpers ----------------
__device__ __forceinline__ uint32_t smem_u32(const void* p) {
    uint32_t a;
    asm("{ .reg .u64 t; cvta.to.shared.u64 t, %1; cvt.u32.u64 %0, t; }" : "=r"(a) : "l"(p));
    return a;
}
__device__ __forceinline__ void ldsm4(uint32_t& r0, uint32_t& r1, uint32_t& r2, uint32_t& r3, uint32_t addr) {
    asm volatile("ldmatrix.sync.aligned.m8n8.x4.shared.b16 {%0,%1,%2,%3}, [%4];"
        : "=r"(r0), "=r"(r1), "=r"(r2), "=r"(r3) : "r"(addr));
}
__device__ __forceinline__ void mma16816(float* d, const uint32_t* a, uint32_t b0, uint32_t b1,
                                         const float* c) {
    asm volatile("mma.sync.aligned.m16n8k16.row.col.f32.bf16.bf16.f32 "
        "{%0,%1,%2,%3}, {%4,%5,%6,%7}, {%8,%9}, {%10,%11,%12,%13};"
        : "=f"(d[0]), "=f"(d[1]), "=f"(d[2]), "=f"(d[3])
        : "r"(a[0]), "r"(a[1]), "r"(a[2]), "r"(a[3]), "r"(b0), "r"(b1),
          "f"(c[0]), "f"(c[1]), "f"(c[2]), "f"(c[3]));
}
__device__ __forceinline__ void cpa16(uint32_t dst, const void* src) {
    asm volatile("cp.async.cg.shared.global [%0], [%1], 16;" :: "r"(dst), "l"(src));
}
#define CP_COMMIT() asm volatile("cp.async.commit_group;" ::: "memory")
#define CP_WAIT(n)  asm volatile("cp.async.wait_group %0;" :: "n"(n) : "memory")

// ============================ GroupNorm ============================
__global__ void __launch_bounds__(256) gn_kernel(const float* __restrict__ x,
                                                 const float* __restrict__ gamma,
                                                 const float* __restrict__ beta) {
    const int bg  = blockIdx.x;
    const int tid = threadIdx.x;
    const float* src = x    + (size_t)bg * GRP_ELEMS;
    float*       dst = g_xn + (size_t)bg * GRP_ELEMS;

    float s = 0.f, ss = 0.f;
    const float4* src4 = (const float4*)src;
    for (int i = tid; i < GRP_ELEMS/4; i += 256) {
        float4 v = src4[i];
        s  += v.x + v.y + v.z + v.w;
        ss += v.x*v.x + v.y*v.y + v.z*v.z + v.w*v.w;
    }
    __shared__ float rs[256], rss[256];
    rs[tid] = s; rss[tid] = ss;
    __syncthreads();
    for (int o = 128; o > 0; o >>= 1) {
        if (tid < o) { rs[tid] += rs[tid+o]; rss[tid] += rss[tid+o]; }
        __syncthreads();
    }
    const float mean = rs[0]  * (1.f/GRP_ELEMS);
    const float var  = rss[0] * (1.f/GRP_ELEMS) - mean*mean;
    const float rstd = rsqrtf(var + 1e-5f);
    const int c0 = (bg % NG) * CPG;

    float4* dst4 = (float4*)dst;
    for (int i = tid; i < GRP_ELEMS/4; i += 256) {
        const int c = c0 + (i*4)/HW;
        const float ga = gamma[c], be = beta[c];
        float4 v = src4[i];
        v.x = (v.x-mean)*rstd*ga + be;
        v.y = (v.y-mean)*rstd*ga + be;
        v.z = (v.z-mean)*rstd*ga + be;
        v.w = (v.w-mean)*rstd*ga + be;
        dst4[i] = v;
    }
}

// ============================ QKV GEMM -> bf16 layouts ============================
#define SA 132
#define SB 132
#define SM_GEMM (2*128*132*sizeof(float))

__global__ void __launch_bounds__(256) qkv_kernel(const float* __restrict__ W,
                                                  const float* __restrict__ bias) {
    const int b  = blockIdx.z;
    const int yb = blockIdx.y;            // 0=Q, 1=K, 2=V
    const int o0 = yb * 128;
    const int p0 = blockIdx.x * 128;
    extern __shared__ float sm[];
    float* As = sm;
    float* Bs = sm + 128*SA;
    const int tid = threadIdx.x;

    for (int idx = tid*4; idx < 128*128; idx += 1024) {
        const int o = idx >> 7, c = idx & 127;
        float4 w = *(const float4*)&W[(size_t)(o0+o)*CH + c];
        As[(c+0)*SA + o] = w.x; As[(c+1)*SA + o] = w.y;
        As[(c+2)*SA + o] = w.z; As[(c+3)*SA + o] = w.w;
    }
    const float* xb = g_xn + (size_t)b*CH*HW;
    for (int idx = tid*4; idx < 128*128; idx += 1024) {
        const int c = idx >> 7, p = idx & 127;
        *(float4*)&Bs[c*SB + p] = *(const float4*)&xb[(size_t)c*HW + p0 + p];
    }
    __syncthreads();

    const int tx = tid & 15, ty = tid >> 4;
    unsigned long long acc[8][4];
#pragma unroll
    for (int i = 0; i < 8; i++)
#pragma unroll
        for (int j = 0; j < 4; j++) acc[i][j] = 0ull;

#pragma unroll 4
    for (int c = 0; c < 128; c++) {
        float4 a0 = *(const float4*)&As[c*SA + ty*8];
        float4 a1 = *(const float4*)&As[c*SA + ty*8 + 4];
        longlong2 kb0 = *(const longlong2*)&Bs[c*SB + tx*8];
        longlong2 kb1 = *(const longlong2*)&Bs[c*SB + tx*8 + 4];
        const unsigned long long b0=(unsigned long long)kb0.x, b1=(unsigned long long)kb0.y;
        const unsigned long long b2=(unsigned long long)kb1.x, b3=(unsigned long long)kb1.y;
        const float av[8] = {a0.x,a0.y,a0.z,a0.w,a1.x,a1.y,a1.z,a1.w};
#pragma unroll
        for (int i = 0; i < 8; i++) {
            unsigned long long aa = pk2(av[i], av[i]);
            fma2(acc[i][0], aa, b0); fma2(acc[i][1], aa, b1);
            fma2(acc[i][2], aa, b2); fma2(acc[i][3], aa, b3);
        }
    }

    float vals[8][8];
#pragma unroll
    for (int i = 0; i < 8; i++) {
        const float bo = bias[o0 + ty*8 + i];
#pragma unroll
        for (int j2 = 0; j2 < 4; j2++) {
            float lo, hi; upk2(acc[i][j2], lo, hi);
            vals[i][2*j2]   = lo + bo;
            vals[i][2*j2+1] = hi + bo;
        }
    }

    if (yb < 2) {
        const float sc = (yb == 0) ? SCALE_Q : 1.0f;
        __nv_bfloat16* dst = ((yb == 0) ? g_q : g_k) + (size_t)b*HW*CH;
#pragma unroll
        for (int pj = 0; pj < 8; pj++) {
            const int p = p0 + tx*8 + pj;
            __nv_bfloat16 t[8];
#pragma unroll
            for (int i = 0; i < 8; i++) t[i] = __float2bfloat16(vals[i][pj] * sc);
            *(int4*)&dst[(size_t)p*CH + ty*8] = *(const int4*)t;
        }
    } else {
        __nv_bfloat16* dst = g_v + (size_t)b*CH*HW;
#pragma unroll
        for (int i = 0; i < 8; i++) {
            const int o = ty*8 + i;
            __nv_bfloat16 t[8];
#pragma unroll
            for (int pj = 0; pj < 8; pj++) t[pj] = __float2bfloat16(vals[i][pj]);
            *(int4*)&dst[(size_t)o*HW + p0 + tx*8] = *(const int4*)t;
        }
    }
}

// ============================ mma.sync flash attention ============================
// smem bf16 tiles, stride 136 elems (272 B): Q | K0 | K1 | V0 | V1
#define TSTRIDE 136
#define TILE_B  (128*TSTRIDE*2)          // 34816
#define OFF_Q   0
#define OFF_K0  (TILE_B)
#define OFF_K1  (2*TILE_B)
#define OFF_V0  (3*TILE_B)
#define OFF_V1  (4*TILE_B)
#define SM_FLASH (5*TILE_B)              // 174080

__global__ void __launch_bounds__(256, 1) flash_mma_kernel() {
    extern __shared__ char smem[];
    const uint32_t sbase = smem_u32(smem);

    const int b    = blockIdx.y;
    const int n0   = blockIdx.x * 128;
    const int tid  = threadIdx.x;
    const int w    = tid >> 5;
    const int lane = tid & 31;
    const int g    = lane >> 2;          // group id (row within 8)
    const int qi   = lane & 3;           // quad index

    const char* gq = (const char*)(g_q + (size_t)b*HW*CH);
    const char* gk = (const char*)(g_k + (size_t)b*HW*CH);
    const char* gv = (const char*)(g_v + (size_t)b*CH*HW);

    // ---- prologue: stage Q, then K0/V0 via cp.async ----
    for (int i = 0; i < 8; i++) {
        const int idx = tid + i*256;
        const int r = idx >> 4, c16 = idx & 15;
        cpa16(sbase + OFF_Q + r*272 + c16*16, gq + (size_t)(n0 + r)*256 + c16*16);
    }
    CP_COMMIT();
    for (int i = 0; i < 8; i++) {
        const int idx = tid + i*256;
        const int r = idx >> 4, c16 = idx & 15;
        cpa16(sbase + OFF_K0 + r*272 + c16*16, gk + (size_t)r*256 + c16*16);
    }
    for (int i = 0; i < 8; i++) {
        const int idx = tid + i*256;
        const int r = idx >> 4, c16 = idx & 15;
        cpa16(sbase + OFF_V0 + r*272 + c16*16, gv + (size_t)r*(HW*2) + c16*16);
    }
    CP_COMMIT();
    CP_WAIT(1);
    __syncthreads();

    // ---- load Q fragments (A-frags): row bit = lane>>3 & 1, ch bit = lane>>4 ----
    uint32_t qf[8][4];
    {
        const uint32_t qrow = (uint32_t)(16*w + (lane & 7) + ((lane >> 3) & 1)*8);
        const uint32_t qcoff = (uint32_t)((lane >> 4) * 16);
#pragma unroll
        for (int kk = 0; kk < 8; kk++)
            ldsm4(qf[kk][0], qf[kk][1], qf[kk][2], qf[kk][3],
                  sbase + OFF_Q + qrow*272 + kk*32 + qcoff);
    }

    float oa[16][4];
#pragma unroll
    for (int j = 0; j < 16; j++)
#pragma unroll
        for (int r = 0; r < 4; r++) oa[j][r] = 0.f;
    float rs0 = 0.f, rs1 = 0.f;

    // B-frag per-thread offsets: row bit = lane>>4 & 1, ch bit = lane>>3 & 1
    const uint32_t browoff = (uint32_t)((((lane >> 4) & 1)*8 + (lane & 7))*272);
    const uint32_t bchoff  = (uint32_t)(((lane >> 3) & 1)*16);

    for (int kt = 0; kt < 32; kt++) {
        CP_WAIT(0);
        __syncthreads();

        if (kt < 31) {
            const int m1 = (kt + 1)*128;
            const uint32_t kb = sbase + (((kt + 1) & 1) ? OFF_K1 : OFF_K0);
            const uint32_t vb = sbase + (((kt + 1) & 1) ? OFF_V1 : OFF_V0);
            for (int i = 0; i < 8; i++) {
                const int idx = tid + i*256;
                const int r = idx >> 4, c16 = idx & 15;
                cpa16(kb + r*272 + c16*16, gk + (size_t)(m1 + r)*256 + c16*16);
            }
            for (int i = 0; i < 8; i++) {
                const int idx = tid + i*256;
                const int r = idx >> 4, c16 = idx & 15;
                cpa16(vb + r*272 + c16*16, gv + (size_t)r*(HW*2) + (size_t)m1*2 + c16*16);
            }
            CP_COMMIT();
        }

        const uint32_t kb = sbase + ((kt & 1) ? OFF_K1 : OFF_K0);
        const uint32_t vb = sbase + ((kt & 1) ? OFF_V1 : OFF_V0);

        // ---- S = Q * K^T : sc[16][4] over 16 key-subtiles ----
        float sc[16][4];
#pragma unroll
        for (int j = 0; j < 16; j++)
#pragma unroll
            for (int r = 0; r < 4; r++) sc[j][r] = 0.f;

#pragma unroll
        for (int kk = 0; kk < 8; kk++) {
#pragma unroll
            for (int jp = 0; jp < 8; jp++) {
                uint32_t r0, r1, r2, r3;
                ldsm4(r0, r1, r2, r3, kb + jp*16*272 + browoff + kk*32 + bchoff);
                mma16816(sc[2*jp],   qf[kk], r0, r1, sc[2*jp]);
                mma16816(sc[2*jp+1], qf[kk], r2, r3, sc[2*jp+1]);
            }
        }

        // ---- exp + pack P into A-frags ----
        uint32_t p2[16][2];
#pragma unroll
        for (int j = 0; j < 16; j++) {
            float e0 = __expf(sc[j][0]);
            float e1 = __expf(sc[j][1]);
            float e2 = __expf(sc[j][2]);
            float e3 = __expf(sc[j][3]);
            rs0 += e0 + e1;
            rs1 += e2 + e3;
            __nv_bfloat162 lo = __floats2bfloat162_rn(e0, e1);
            __nv_bfloat162 hi = __floats2bfloat162_rn(e2, e3);
            p2[j][0] = *(const uint32_t*)&lo;
            p2[j][1] = *(const uint32_t*)&hi;
        }

        // ---- O += P * V : V staged [ch][key], non-trans ldmatrix gives B-frags ----
#pragma unroll
        for (int kk = 0; kk < 8; kk++) {
            uint32_t a[4] = { p2[2*kk][0], p2[2*kk][1], p2[2*kk+1][0], p2[2*kk+1][1] };
#pragma unroll
            for (int jp = 0; jp < 8; jp++) {
                uint32_t r0, r1, r2, r3;
                ldsm4(r0, r1, r2, r3, vb + jp*16*272 + browoff + kk*32 + bchoff);
                mma16816(oa[2*jp],   a, r0, r1, oa[2*jp]);
                mma16816(oa[2*jp+1], a, r2, r3, oa[2*jp+1]);
            }
        }
    }

    // ---- epilogue: reduce rsum across quad, normalize, transpose via smem ----
    rs0 += __shfl_xor_sync(0xffffffffu, rs0, 1);
    rs0 += __shfl_xor_sync(0xffffffffu, rs0, 2);
    rs1 += __shfl_xor_sync(0xffffffffu, rs1, 1);
    rs1 += __shfl_xor_sync(0xffffffffu, rs1, 2);
    const float inv0 = 1.0f / rs0;
    const float inv1 = 1.0f / rs1;

    __syncthreads();                          // all compute done before Ts overlay
    float* Ts = (float*)smem;                 // [ch][query], stride 132 (67.6 KB over Q+K0)
#pragma unroll
    for (int j = 0; j < 16; j++) {
        const int ch0 = 8*j + 2*qi;
        const int q0 = 16*w + g;
        Ts[(ch0  )*132 + q0    ] = oa[j][0]*inv0;
        Ts[(ch0+1)*132 + q0    ] = oa[j][1]*inv0;
        Ts[(ch0  )*132 + q0 + 8] = oa[j][2]*inv1;
        Ts[(ch0+1)*132 + q0 + 8] = oa[j][3]*inv1;
    }
    __syncthreads();
    float* ab = g_attn + (size_t)b*CH*HW;
    for (int idx = tid*4; idx < 128*128; idx += 1024) {
        const int ch = idx >> 7, n = idx & 127;
        *(float4*)&ab[(size_t)ch*HW + n0 + n] = *(const float4*)&Ts[ch*132 + n];
    }
}

// ================== Output GEMM + bias + residual ==================
__global__ void __launch_bounds__(256) out_kernel(const float* __restrict__ W,
                                                  const float* __restrict__ bias,
                                                  const float* __restrict__ x,
                                                  float* __restrict__ out) {
    const int b  = blockIdx.y;
    const int p0 = blockIdx.x * 128;
    extern __shared__ float sm[];
    float* As = sm;
    float* Bs = sm + 128*SA;
    const int tid = threadIdx.x;

    for (int idx = tid*4; idx < 128*128; idx += 1024) {
        const int o = idx >> 7, c = idx & 127;
        float4 w = *(const float4*)&W[(size_t)o*CH + c];
        As[(c+0)*SA + o] = w.x; As[(c+1)*SA + o] = w.y;
        As[(c+2)*SA + o] = w.z; As[(c+3)*SA + o] = w.w;
    }
    const float* ab = g_attn + (size_t)b*CH*HW;
    for (int idx = tid*4; idx < 128*128; idx += 1024) {
        const int c = idx >> 7, p = idx & 127;
        *(float4*)&Bs[c*SB + p] = *(const float4*)&ab[(size_t)c*HW + p0 + p];
    }
    __syncthreads();

    const int tx = tid & 15, ty = tid >> 4;
    unsigned long long acc[8][4];
#pragma unroll
    for (int i = 0; i < 8; i++)
#pragma unroll
        for (int j = 0; j < 4; j++) acc[i][j] = 0ull;

#pragma unroll 4
    for (int c = 0; c < 128; c++) {
        float4 a0 = *(const float4*)&As[c*SA + ty*8];
        float4 a1 = *(const float4*)&As[c*SA + ty*8 + 4];
        longlong2 kb0 = *(const longlong2*)&Bs[c*SB + tx*8];
        longlong2 kb1 = *(const longlong2*)&Bs[c*SB + tx*8 + 4];
        const unsigned long long b0=(unsigned long long)kb0.x, b1=(unsigned long long)kb0.y;
        const unsigned long long b2=(unsigned long long)kb1.x, b3=(unsigned long long)kb1.y;
        const float av[8] = {a0.x,a0.y,a0.z,a0.w,a1.x,a1.y,a1.z,a1.w};
#pragma unroll
        for (int i = 0; i < 8; i++) {
            unsigned long long aa = pk2(av[i], av[i]);
            fma2(acc[i][0], aa, b0); fma2(acc[i][1], aa, b1);
            fma2(acc[i][2], aa, b2); fma2(acc[i][3], aa, b3);
        }
    }

#pragma unroll
    for (int i = 0; i < 8; i++) {
        const int o = ty*8 + i;
        const float bo = bias[o];
        const size_t rowg = ((size_t)b*CH + o)*HW + p0;
#pragma unroll
        for (int j2 = 0; j2 < 4; j2++) {
            float lo, hi; upk2(acc[i][j2], lo, hi);
            float2 xr = *(const float2*)&x[rowg + tx*8 + 2*j2];
            float2 v; v.x = lo + bo + xr.x; v.y = hi + bo + xr.y;
            *(float2*)&out[rowg + tx*8 + 2*j2] = v;
        }
    }
}

// ===================================================================
extern "C" void kernel_launch(void* const* d_in, const int* in_sizes, int n_in,
                              void* d_out, int out_size) {
    const float* x     = (const float*)d_in[0];
    const float* gamma = (const float*)d_in[1];
    const float* beta  = (const float*)d_in[2];
    const float* w_qkv = (const float*)d_in[3];
    const float* b_qkv = (const float*)d_in[4];
    const float* w_out = (const float*)d_in[5];
    const float* b_out = (const float*)d_in[6];
    float*       out   = (float*)d_out;

    cudaFuncSetAttribute(qkv_kernel,      cudaFuncAttributeMaxDynamicSharedMemorySize, (int)SM_GEMM);
    cudaFuncSetAttribute(flash_mma_kernel,cudaFuncAttributeMaxDynamicSharedMemorySize, (int)SM_FLASH);
    cudaFuncSetAttribute(out_kernel,      cudaFuncAttributeMaxDynamicSharedMemorySize, (int)SM_GEMM);

    gn_kernel<<<BATCH*NG, 256>>>(x, gamma, beta);

    dim3 gq(HW/128, 3, BATCH);
    qkv_kernel<<<gq, 256, SM_GEMM>>>(w_qkv, b_qkv);

    dim3 gf(HW/128, BATCH);
    flash_mma_kernel<<<gf, 256, SM_FLASH>>>();

    dim3 go(HW/128, BATCH);
    out_kernel<<<go, 256, SM_GEMM>>>(w_out, b_out, x, out);
}

// round 7
// speedup vs baseline: 7.2253x; 1.4253x over previous
#include <cuda_runtime.h>
#include <cuda_bf16.h>
#include <cstdint>

#define BATCH 8
#define CH    128
#define HW    4096
#define NG    32
#define CPG   4
#define GRP_ELEMS (CPG*HW)
#define SCALE_Q 0.08838834764831845f   // 1/sqrt(128)

__device__ __nv_bfloat16 g_xnt [BATCH*HW*CH];   // [b][p][c] groupnormed, bf16
__device__ __nv_bfloat16 g_q   [BATCH*HW*CH];   // [b][n][c], scale folded
__device__ __nv_bfloat16 g_k   [BATCH*HW*CH];   // [b][m][c]
__device__ __nv_bfloat16 g_v   [BATCH*CH*HW];   // [b][c][m]
__device__ __nv_bfloat16 g_at  [BATCH*HW*CH];   // [b][n][c] attention out
__device__ float2        g_stats[BATCH*NG];     // mean, rstd per (b,g)

// ---------------- mma.sync / ldmatrix / cp.async helpers ----------------
__device__ __forceinline__ uint32_t smem_u32(const void* p) {
    uint32_t a;
    asm("{ .reg .u64 t; cvta.to.shared.u64 t, %1; cvt.u32.u64 %0, t; }" : "=r"(a) : "l"(p));
    return a;
}
__device__ __forceinline__ void ldsm4(uint32_t& r0, uint32_t& r1, uint32_t& r2, uint32_t& r3, uint32_t addr) {
    asm volatile("ldmatrix.sync.aligned.m8n8.x4.shared.b16 {%0,%1,%2,%3}, [%4];"
        : "=r"(r0), "=r"(r1), "=r"(r2), "=r"(r3) : "r"(addr));
}
__device__ __forceinline__ void mma16816(float* d, const uint32_t* a, uint32_t b0, uint32_t b1,
                                         const float* c) {
    asm volatile("mma.sync.aligned.m16n8k16.row.col.f32.bf16.bf16.f32 "
        "{%0,%1,%2,%3}, {%4,%5,%6,%7}, {%8,%9}, {%10,%11,%12,%13};"
        : "=f"(d[0]), "=f"(d[1]), "=f"(d[2]), "=f"(d[3])
        : "r"(a[0]), "r"(a[1]), "r"(a[2]), "r"(a[3]), "r"(b0), "r"(b1),
          "f"(c[0]), "f"(c[1]), "f"(c[2]), "f"(c[3]));
}
__device__ __forceinline__ void cpa16(uint32_t dst, const void* src) {
    asm volatile("cp.async.cg.shared.global [%0], [%1], 16;" :: "r"(dst), "l"(src));
}
#define CP_COMMIT() asm volatile("cp.async.commit_group;" ::: "memory")
#define CP_WAIT(n)  asm volatile("cp.async.wait_group %0;" :: "n"(n) : "memory")

__device__ __forceinline__ uint32_t bf2bits(__nv_bfloat162 v) { return *(const uint32_t*)&v; }

// ============================ GroupNorm stats ============================
__global__ void __launch_bounds__(256) gn_stats_kernel(const float* __restrict__ x) {
    const int bg  = blockIdx.x;
    const int tid = threadIdx.x;
    const float4* src4 = (const float4*)(x + (size_t)bg * GRP_ELEMS);

    float s = 0.f, ss = 0.f;
    for (int i = tid; i < GRP_ELEMS/4; i += 256) {
        float4 v = src4[i];
        s  += v.x + v.y + v.z + v.w;
        ss += v.x*v.x + v.y*v.y + v.z*v.z + v.w*v.w;
    }
    __shared__ float rs[256], rss[256];
    rs[tid] = s; rss[tid] = ss;
    __syncthreads();
    for (int o = 128; o > 0; o >>= 1) {
        if (tid < o) { rs[tid] += rs[tid+o]; rss[tid] += rss[tid+o]; }
        __syncthreads();
    }
    if (tid == 0) {
        const float mean = rs[0]  * (1.f/GRP_ELEMS);
        const float var  = rss[0] * (1.f/GRP_ELEMS) - mean*mean;
        g_stats[bg] = make_float2(mean, rsqrtf(var + 1e-5f));
    }
}

// ============================ GroupNorm apply + transpose -> bf16 [p][c] ============================
__global__ void __launch_bounds__(256) gn_apply_kernel(const float* __restrict__ x,
                                                       const float* __restrict__ gamma,
                                                       const float* __restrict__ beta) {
    const int b   = blockIdx.y;
    const int p0  = blockIdx.x * 128;
    const int tid = threadIdx.x;
    __shared__ __nv_bfloat16 Xs[128*136];
    __shared__ float scl[128], sft[128];

    if (tid < 128) {
        float2 st = g_stats[b*NG + (tid >> 2)];
        const float sc = st.y * gamma[tid];
        scl[tid] = sc;
        sft[tid] = beta[tid] - st.x * sc;
    }
    __syncthreads();

    const int p    = tid & 127;
    const int half = tid >> 7;
    const float* xb = x + (size_t)b*CH*HW + p0 + p;
#pragma unroll
    for (int cg = 0; cg < 16; cg++) {
        const int c = half*64 + cg*4;
        float v0 = xb[(size_t)(c+0)*HW]*scl[c+0] + sft[c+0];
        float v1 = xb[(size_t)(c+1)*HW]*scl[c+1] + sft[c+1];
        float v2 = xb[(size_t)(c+2)*HW]*scl[c+2] + sft[c+2];
        float v3 = xb[(size_t)(c+3)*HW]*scl[c+3] + sft[c+3];
        uint2 u;
        u.x = bf2bits(__floats2bfloat162_rn(v0, v1));
        u.y = bf2bits(__floats2bfloat162_rn(v2, v3));
        *(uint2*)&Xs[p*136 + c] = u;
    }
    __syncthreads();

    __nv_bfloat16* dst = g_xnt + ((size_t)b*HW + p0)*CH;
    for (int i = tid; i < 2048; i += 256) {
        const int pr = i >> 4, c16 = i & 15;
        *(int4*)&dst[(size_t)pr*CH + c16*8] = *(const int4*)&Xs[pr*136 + c16*8];
    }
}

// ============================ QKV GEMM (mma.sync bf16) ============================
// yb 0/1 (Q/K): C[p][o] = xn[p][:]·W[o][:]  -> g_q/g_k [p][c]
// yb 2   (V)  : C[o][p] = W[o][:]·xn[p][:]  -> g_v [c][m]
#define SM_MMA (2*128*136*2)   // 69632 B

__global__ void __launch_bounds__(256) qkv_mma_kernel(const float* __restrict__ W,
                                                      const float* __restrict__ bias) {
    const int b  = blockIdx.z;
    const int yb = blockIdx.y;
    const int p0 = blockIdx.x * 128;
    const int tid = threadIdx.x;
    const int w = tid >> 5, lane = tid & 31;
    const int g = lane >> 2, qi = lane & 3;
    extern __shared__ char smraw[];
    __nv_bfloat16* As = (__nv_bfloat16*)smraw;
    __nv_bfloat16* Bs = As + 128*136;
    const bool vmode = (yb == 2);

    // stage xn tile [p][c]
    {
        __nv_bfloat16* Xs = vmode ? Bs : As;
        const __nv_bfloat16* xn = g_xnt + ((size_t)b*HW + p0)*CH;
        for (int i = tid; i < 2048; i += 256) {
            const int r = i >> 4, c16 = i & 15;
            *(int4*)&Xs[r*136 + c16*8] = *(const int4*)&xn[(size_t)r*CH + c16*8];
        }
    }
    // stage W tile [o][c], fp32 -> bf16
    {
        __nv_bfloat16* Ws = vmode ? As : Bs;
        const float* Wt = W + (size_t)yb*128*CH;
        for (int i = tid; i < 4096; i += 256) {
            const int r = i >> 5, c4 = (i & 31)*4;
            float4 wv = *(const float4*)&Wt[(size_t)r*CH + c4];
            uint2 u;
            u.x = bf2bits(__floats2bfloat162_rn(wv.x, wv.y));
            u.y = bf2bits(__floats2bfloat162_rn(wv.z, wv.w));
            *(uint2*)&Ws[r*136 + c4] = u;
        }
    }
    __syncthreads();

    const uint32_t abase = smem_u32(As);
    const uint32_t bbase = smem_u32(Bs);

    // A-frags
    uint32_t af[8][4];
    {
        const uint32_t arow = (uint32_t)(16*w + (lane & 7) + ((lane >> 3) & 1)*8);
        const uint32_t acoff = (uint32_t)((lane >> 4)*16);
#pragma unroll
        for (int kk = 0; kk < 8; kk++)
            ldsm4(af[kk][0], af[kk][1], af[kk][2], af[kk][3],
                  abase + arow*272 + kk*32 + acoff);
    }

    float cf[16][4];
#pragma unroll
    for (int j = 0; j < 16; j++)
#pragma unroll
        for (int r = 0; r < 4; r++) cf[j][r] = 0.f;

    const uint32_t browoff = (uint32_t)((((lane >> 4) & 1)*8 + (lane & 7))*272);
    const uint32_t bchoff  = (uint32_t)(((lane >> 3) & 1)*16);

#pragma unroll
    for (int kk = 0; kk < 8; kk++) {
#pragma unroll
        for (int jp = 0; jp < 8; jp++) {
            uint32_t r0, r1, r2, r3;
            ldsm4(r0, r1, r2, r3, bbase + jp*16*272 + browoff + kk*32 + bchoff);
            mma16816(cf[2*jp],   af[kk], r0, r1, cf[2*jp]);
            mma16816(cf[2*jp+1], af[kk], r2, r3, cf[2*jp+1]);
        }
    }

    if (!vmode) {
        const float sc = (yb == 0) ? SCALE_Q : 1.0f;
        __nv_bfloat16* dst = ((yb == 0) ? g_q : g_k) + (size_t)b*HW*CH;
        const int row0 = p0 + 16*w + g;
#pragma unroll
        for (int j = 0; j < 16; j++) {
            const int col = 8*j + 2*qi;
            const float b0 = __ldg(&bias[yb*128 + col]);
            const float b1 = __ldg(&bias[yb*128 + col + 1]);
            *(uint32_t*)&dst[(size_t)row0*CH + col] =
                bf2bits(__floats2bfloat162_rn((cf[j][0]+b0)*sc, (cf[j][1]+b1)*sc));
            *(uint32_t*)&dst[(size_t)(row0+8)*CH + col] =
                bf2bits(__floats2bfloat162_rn((cf[j][2]+b0)*sc, (cf[j][3]+b1)*sc));
        }
    } else {
        __nv_bfloat16* dst = g_v + (size_t)b*CH*HW;
        const int o = 16*w + g;
        const float b0 = __ldg(&bias[256 + o]);
        const float b1 = __ldg(&bias[256 + o + 8]);
#pragma unroll
        for (int j = 0; j < 16; j++) {
            const int p = p0 + 8*j + 2*qi;
            *(uint32_t*)&dst[(size_t)o*HW + p] =
                bf2bits(__floats2bfloat162_rn(cf[j][0]+b0, cf[j][1]+b0));
            *(uint32_t*)&dst[(size_t)(o+8)*HW + p] =
                bf2bits(__floats2bfloat162_rn(cf[j][2]+b1, cf[j][3]+b1));
        }
    }
}

// ============================ mma.sync flash attention ============================
#define TSTRIDE 136
#define TILE_B  (128*TSTRIDE*2)
#define OFF_Q   0
#define OFF_K0  (TILE_B)
#define OFF_K1  (2*TILE_B)
#define OFF_V0  (3*TILE_B)
#define OFF_V1  (4*TILE_B)
#define SM_FLASH (5*TILE_B)

__global__ void __launch_bounds__(256, 1) flash_mma_kernel() {
    extern __shared__ char smem[];
    const uint32_t sbase = smem_u32(smem);

    const int b    = blockIdx.y;
    const int n0   = blockIdx.x * 128;
    const int tid  = threadIdx.x;
    const int w    = tid >> 5;
    const int lane = tid & 31;
    const int g    = lane >> 2;
    const int qi   = lane & 3;

    const char* gq = (const char*)(g_q + (size_t)b*HW*CH);
    const char* gk = (const char*)(g_k + (size_t)b*HW*CH);
    const char* gv = (const char*)(g_v + (size_t)b*CH*HW);

    for (int i = 0; i < 8; i++) {
        const int idx = tid + i*256;
        const int r = idx >> 4, c16 = idx & 15;
        cpa16(sbase + OFF_Q + r*272 + c16*16, gq + (size_t)(n0 + r)*256 + c16*16);
    }
    CP_COMMIT();
    for (int i = 0; i < 8; i++) {
        const int idx = tid + i*256;
        const int r = idx >> 4, c16 = idx & 15;
        cpa16(sbase + OFF_K0 + r*272 + c16*16, gk + (size_t)r*256 + c16*16);
    }
    for (int i = 0; i < 8; i++) {
        const int idx = tid + i*256;
        const int r = idx >> 4, c16 = idx & 15;
        cpa16(sbase + OFF_V0 + r*272 + c16*16, gv + (size_t)r*(HW*2) + c16*16);
    }
    CP_COMMIT();
    CP_WAIT(1);
    __syncthreads();

    uint32_t qf[8][4];
    {
        const uint32_t qrow = (uint32_t)(16*w + (lane & 7) + ((lane >> 3) & 1)*8);
        const uint32_t qcoff = (uint32_t)((lane >> 4) * 16);
#pragma unroll
        for (int kk = 0; kk < 8; kk++)
            ldsm4(qf[kk][0], qf[kk][1], qf[kk][2], qf[kk][3],
                  sbase + OFF_Q + qrow*272 + kk*32 + qcoff);
    }

    float oa[16][4];
#pragma unroll
    for (int j = 0; j < 16; j++)
#pragma unroll
        for (int r = 0; r < 4; r++) oa[j][r] = 0.f;
    float rs0 = 0.f, rs1 = 0.f;

    const uint32_t browoff = (uint32_t)((((lane >> 4) & 1)*8 + (lane & 7))*272);
    const uint32_t bchoff  = (uint32_t)(((lane >> 3) & 1)*16);

    for (int kt = 0; kt < 32; kt++) {
        CP_WAIT(0);
        __syncthreads();

        if (kt < 31) {
            const int m1 = (kt + 1)*128;
            const uint32_t kb = sbase + (((kt + 1) & 1) ? OFF_K1 : OFF_K0);
            const uint32_t vb = sbase + (((kt + 1) & 1) ? OFF_V1 : OFF_V0);
            for (int i = 0; i < 8; i++) {
                const int idx = tid + i*256;
                const int r = idx >> 4, c16 = idx & 15;
                cpa16(kb + r*272 + c16*16, gk + (size_t)(m1 + r)*256 + c16*16);
            }
            for (int i = 0; i < 8; i++) {
                const int idx = tid + i*256;
                const int r = idx >> 4, c16 = idx & 15;
                cpa16(vb + r*272 + c16*16, gv + (size_t)r*(HW*2) + (size_t)m1*2 + c16*16);
            }
            CP_COMMIT();
        }

        const uint32_t kb = sbase + ((kt & 1) ? OFF_K1 : OFF_K0);
        const uint32_t vb = sbase + ((kt & 1) ? OFF_V1 : OFF_V0);

        float sc[16][4];
#pragma unroll
        for (int j = 0; j < 16; j++)
#pragma unroll
            for (int r = 0; r < 4; r++) sc[j][r] = 0.f;

#pragma unroll
        for (int kk = 0; kk < 8; kk++) {
#pragma unroll
            for (int jp = 0; jp < 8; jp++) {
                uint32_t r0, r1, r2, r3;
                ldsm4(r0, r1, r2, r3, kb + jp*16*272 + browoff + kk*32 + bchoff);
                mma16816(sc[2*jp],   qf[kk], r0, r1, sc[2*jp]);
                mma16816(sc[2*jp+1], qf[kk], r2, r3, sc[2*jp+1]);
            }
        }

        uint32_t p2[16][2];
#pragma unroll
        for (int j = 0; j < 16; j++) {
            float e0 = __expf(sc[j][0]);
            float e1 = __expf(sc[j][1]);
            float e2 = __expf(sc[j][2]);
            float e3 = __expf(sc[j][3]);
            rs0 += e0 + e1;
            rs1 += e2 + e3;
            p2[j][0] = bf2bits(__floats2bfloat162_rn(e0, e1));
            p2[j][1] = bf2bits(__floats2bfloat162_rn(e2, e3));
        }

#pragma unroll
        for (int kk = 0; kk < 8; kk++) {
            uint32_t a[4] = { p2[2*kk][0], p2[2*kk][1], p2[2*kk+1][0], p2[2*kk+1][1] };
#pragma unroll
            for (int jp = 0; jp < 8; jp++) {
                uint32_t r0, r1, r2, r3;
                ldsm4(r0, r1, r2, r3, vb + jp*16*272 + browoff + kk*32 + bchoff);
                mma16816(oa[2*jp],   a, r0, r1, oa[2*jp]);
                mma16816(oa[2*jp+1], a, r2, r3, oa[2*jp+1]);
            }
        }
    }

    rs0 += __shfl_xor_sync(0xffffffffu, rs0, 1);
    rs0 += __shfl_xor_sync(0xffffffffu, rs0, 2);
    rs1 += __shfl_xor_sync(0xffffffffu, rs1, 1);
    rs1 += __shfl_xor_sync(0xffffffffu, rs1, 2);
    const float inv0 = 1.0f / rs0;
    const float inv1 = 1.0f / rs1;

    // write O directly as bf16 [n][c]
    __nv_bfloat16* ao = g_at + ((size_t)b*HW + n0)*CH;
    const int q0 = 16*w + g;
#pragma unroll
    for (int j = 0; j < 16; j++) {
        const int ch = 8*j + 2*qi;
        *(uint32_t*)&ao[(size_t)q0*CH + ch] =
            bf2bits(__floats2bfloat162_rn(oa[j][0]*inv0, oa[j][1]*inv0));
        *(uint32_t*)&ao[(size_t)(q0+8)*CH + ch] =
            bf2bits(__floats2bfloat162_rn(oa[j][2]*inv1, oa[j][3]*inv1));
    }
}

// ================== Output GEMM (mma.sync) + bias + residual ==================
// C[o][p] = W[o][:]·attn[p][:] ; out = C + bias[o] + x
__global__ void __launch_bounds__(256) out_mma_kernel(const float* __restrict__ W,
                                                      const float* __restrict__ bias,
                                                      const float* __restrict__ x,
                                                      float* __restrict__ out) {
    const int b  = blockIdx.y;
    const int p0 = blockIdx.x * 128;
    const int tid = threadIdx.x;
    const int w = tid >> 5, lane = tid & 31;
    const int g = lane >> 2, qi = lane & 3;
    extern __shared__ char smraw[];
    __nv_bfloat16* As = (__nv_bfloat16*)smraw;          // W [o][c]
    __nv_bfloat16* Bs = As + 128*136;                   // attn [p][c]

    for (int i = tid; i < 4096; i += 256) {
        const int r = i >> 5, c4 = (i & 31)*4;
        float4 wv = *(const float4*)&W[(size_t)r*CH + c4];
        uint2 u;
        u.x = bf2bits(__floats2bfloat162_rn(wv.x, wv.y));
        u.y = bf2bits(__floats2bfloat162_rn(wv.z, wv.w));
        *(uint2*)&As[r*136 + c4] = u;
    }
    const __nv_bfloat16* at = g_at + ((size_t)b*HW + p0)*CH;
    for (int i = tid; i < 2048; i += 256) {
        const int r = i >> 4, c16 = i & 15;
        *(int4*)&Bs[r*136 + c16*8] = *(const int4*)&at[(size_t)r*CH + c16*8];
    }
    __syncthreads();

    const uint32_t abase = smem_u32(As);
    const uint32_t bbase = smem_u32(Bs);

    uint32_t af[8][4];
    {
        const uint32_t arow = (uint32_t)(16*w + (lane & 7) + ((lane >> 3) & 1)*8);
        const uint32_t acoff = (uint32_t)((lane >> 4)*16);
#pragma unroll
        for (int kk = 0; kk < 8; kk++)
            ldsm4(af[kk][0], af[kk][1], af[kk][2], af[kk][3],
                  abase + arow*272 + kk*32 + acoff);
    }

    float cf[16][4];
#pragma unroll
    for (int j = 0; j < 16; j++)
#pragma unroll
        for (int r = 0; r < 4; r++) cf[j][r] = 0.f;

    const uint32_t browoff = (uint32_t)((((lane >> 4) & 1)*8 + (lane & 7))*272);
    const uint32_t bchoff  = (uint32_t)(((lane >> 3) & 1)*16);

#pragma unroll
    for (int kk = 0; kk < 8; kk++) {
#pragma unroll
        for (int jp = 0; jp < 8; jp++) {
            uint32_t r0, r1, r2, r3;
            ldsm4(r0, r1, r2, r3, bbase + jp*16*272 + browoff + kk*32 + bchoff);
            mma16816(cf[2*jp],   af[kk], r0, r1, cf[2*jp]);
            mma16816(cf[2*jp+1], af[kk], r2, r3, cf[2*jp+1]);
        }
    }

    const int o = 16*w + g;
    const float b0 = __ldg(&bias[o]);
    const float b1 = __ldg(&bias[o + 8]);
    const size_t row0 = ((size_t)b*CH + o)*HW + p0;
    const size_t row1 = ((size_t)b*CH + o + 8)*HW + p0;
#pragma unroll
    for (int j = 0; j < 16; j++) {
        const int p = 8*j + 2*qi;
        float2 x0 = *(const float2*)&x[row0 + p];
        float2 x1 = *(const float2*)&x[row1 + p];
        float2 v0; v0.x = cf[j][0] + b0 + x0.x; v0.y = cf[j][1] + b0 + x0.y;
        float2 v1; v1.x = cf[j][2] + b1 + x1.x; v1.y = cf[j][3] + b1 + x1.y;
        *(float2*)&out[row0 + p] = v0;
        *(float2*)&out[row1 + p] = v1;
    }
}

// ===================================================================
extern "C" void kernel_launch(void* const* d_in, const int* in_sizes, int n_in,
                              void* d_out, int out_size) {
    const float* x     = (const float*)d_in[0];
    const float* gamma = (const float*)d_in[1];
    const float* beta  = (const float*)d_in[2];
    const float* w_qkv = (const float*)d_in[3];
    const float* b_qkv = (const float*)d_in[4];
    const float* w_out = (const float*)d_in[5];
    const float* b_out = (const float*)d_in[6];
    float*       out   = (float*)d_out;

    cudaFuncSetAttribute(qkv_mma_kernel,  cudaFuncAttributeMaxDynamicSharedMemorySize, (int)SM_MMA);
    cudaFuncSetAttribute(flash_mma_kernel,cudaFuncAttributeMaxDynamicSharedMemorySize, (int)SM_FLASH);
    cudaFuncSetAttribute(out_mma_kernel,  cudaFuncAttributeMaxDynamicSharedMemorySize, (int)SM_MMA);

    gn_stats_kernel<<<BATCH*NG, 256>>>(x);

    dim3 ga(HW/128, BATCH);
    gn_apply_kernel<<<ga, 256>>>(x, gamma, beta);

    dim3 gq(HW/128, 3, BATCH);
    qkv_mma_kernel<<<gq, 256, SM_MMA>>>(w_qkv, b_qkv);

    dim3 gf(HW/128, BATCH);
    flash_mma_kernel<<<gf, 256, SM_FLASH>>>();

    dim3 go(HW/128, BATCH);
    out_mma_kernel<<<go, 256, SM_MMA>>>(w_out, b_out, x, out);
}

// round 9
// speedup vs baseline: 7.7298x; 1.0698x over previous
#include <cuda_runtime.h>
#include <cuda_bf16.h>
#include <cstdint>

#define BATCH 8
#define CH    128
#define HW    4096
#define NG    32
#define CPG   4
#define GRP_ELEMS (CPG*HW)
// 1/sqrt(128) * log2(e): softmax done with ex2 (e^S = 2^(S*log2e))
#define SCALE_QL2E (0.08838834764831845f * 1.4426950408889634f)

__device__ __nv_bfloat16 g_xnt [BATCH*HW*CH];   // [b][p][c] groupnormed, bf16
__device__ __nv_bfloat16 g_q   [BATCH*HW*CH];   // [b][n][c], scale*log2e folded
__device__ __nv_bfloat16 g_k   [BATCH*HW*CH];   // [b][m][c]
__device__ __nv_bfloat16 g_v   [BATCH*CH*HW];   // [b][c][m]
__device__ __nv_bfloat16 g_at  [BATCH*HW*CH];   // [b][n][c] attention out
__device__ float2        g_stats[BATCH*NG];     // mean, rstd per (b,g)

// ---------------- mma.sync / ldmatrix / cp.async helpers ----------------
__device__ __forceinline__ uint32_t smem_u32(const void* p) {
    uint32_t a;
    asm("{ .reg .u64 t; cvta.to.shared.u64 t, %1; cvt.u32.u64 %0, t; }" : "=r"(a) : "l"(p));
    return a;
}
__device__ __forceinline__ void ldsm4(uint32_t& r0, uint32_t& r1, uint32_t& r2, uint32_t& r3, uint32_t addr) {
    asm volatile("ldmatrix.sync.aligned.m8n8.x4.shared.b16 {%0,%1,%2,%3}, [%4];"
        : "=r"(r0), "=r"(r1), "=r"(r2), "=r"(r3) : "r"(addr));
}
__device__ __forceinline__ void mma16816(float* d, const uint32_t* a, uint32_t b0, uint32_t b1,
                                         const float* c) {
    asm volatile("mma.sync.aligned.m16n8k16.row.col.f32.bf16.bf16.f32 "
        "{%0,%1,%2,%3}, {%4,%5,%6,%7}, {%8,%9}, {%10,%11,%12,%13};"
        : "=f"(d[0]), "=f"(d[1]), "=f"(d[2]), "=f"(d[3])
        : "r"(a[0]), "r"(a[1]), "r"(a[2]), "r"(a[3]), "r"(b0), "r"(b1),
          "f"(c[0]), "f"(c[1]), "f"(c[2]), "f"(c[3]));
}
__device__ __forceinline__ void cpa16(uint32_t dst, const void* src) {
    asm volatile("cp.async.cg.shared.global [%0], [%1], 16;" :: "r"(dst), "l"(src));
}
#define CP_COMMIT() asm volatile("cp.async.commit_group;" ::: "memory")
#define CP_WAIT(n)  asm volatile("cp.async.wait_group %0;" :: "n"(n) : "memory")

__device__ __forceinline__ uint32_t bf2bits(__nv_bfloat162 v) { return *(const uint32_t*)&v; }
__device__ __forceinline__ float ex2f(float x) {
    float r; asm("ex2.approx.ftz.f32 %0, %1;" : "=f"(r) : "f"(x)); return r;
}

// ============================ GroupNorm stats ============================
__global__ void __launch_bounds__(256) gn_stats_kernel(const float* __restrict__ x) {
    const int bg  = blockIdx.x;
    const int tid = threadIdx.x;
    const float4* src4 = (const float4*)(x + (size_t)bg * GRP_ELEMS);

    float s = 0.f, ss = 0.f;
    for (int i = tid; i < GRP_ELEMS/4; i += 256) {
        float4 v = src4[i];
        s  += v.x + v.y + v.z + v.w;
        ss += v.x*v.x + v.y*v.y + v.z*v.z + v.w*v.w;
    }
    __shared__ float rs[256], rss[256];
    rs[tid] = s; rss[tid] = ss;
    __syncthreads();
    for (int o = 128; o > 0; o >>= 1) {
        if (tid < o) { rs[tid] += rs[tid+o]; rss[tid] += rss[tid+o]; }
        __syncthreads();
    }
    if (tid == 0) {
        const float mean = rs[0]  * (1.f/GRP_ELEMS);
        const float var  = rss[0] * (1.f/GRP_ELEMS) - mean*mean;
        g_stats[bg] = make_float2(mean, rsqrtf(var + 1e-5f));
    }
}

// ============================ GroupNorm apply + transpose -> bf16 [p][c] ============================
__global__ void __launch_bounds__(256) gn_apply_kernel(const float* __restrict__ x,
                                                       const float* __restrict__ gamma,
                                                       const float* __restrict__ beta) {
    const int b   = blockIdx.y;
    const int p0  = blockIdx.x * 128;
    const int tid = threadIdx.x;
    __shared__ __nv_bfloat16 Xs[128*136];
    __shared__ float scl[128], sft[128];

    if (tid < 128) {
        float2 st = g_stats[b*NG + (tid >> 2)];
        const float sc = st.y * gamma[tid];
        scl[tid] = sc;
        sft[tid] = beta[tid] - st.x * sc;
    }
    __syncthreads();

    const int p    = tid & 127;
    const int half = tid >> 7;
    const float* xb = x + (size_t)b*CH*HW + p0 + p;
#pragma unroll
    for (int cg = 0; cg < 16; cg++) {
        const int c = half*64 + cg*4;
        float v0 = xb[(size_t)(c+0)*HW]*scl[c+0] + sft[c+0];
        float v1 = xb[(size_t)(c+1)*HW]*scl[c+1] + sft[c+1];
        float v2 = xb[(size_t)(c+2)*HW]*scl[c+2] + sft[c+2];
        float v3 = xb[(size_t)(c+3)*HW]*scl[c+3] + sft[c+3];
        uint2 u;
        u.x = bf2bits(__floats2bfloat162_rn(v0, v1));
        u.y = bf2bits(__floats2bfloat162_rn(v2, v3));
        *(uint2*)&Xs[p*136 + c] = u;
    }
    __syncthreads();

    __nv_bfloat16* dst = g_xnt + ((size_t)b*HW + p0)*CH;
    for (int i = tid; i < 2048; i += 256) {
        const int pr = i >> 4, c16 = i & 15;
        *(int4*)&dst[(size_t)pr*CH + c16*8] = *(const int4*)&Xs[pr*136 + c16*8];
    }
}

// ============================ QKV GEMM (mma.sync bf16) ============================
#define SM_MMA (2*128*136*2)   // 69632 B

__global__ void __launch_bounds__(256) qkv_mma_kernel(const float* __restrict__ W,
                                                      const float* __restrict__ bias) {
    const int b  = blockIdx.z;
    const int yb = blockIdx.y;
    const int p0 = blockIdx.x * 128;
    const int tid = threadIdx.x;
    const int w = tid >> 5, lane = tid & 31;
    const int g = lane >> 2, qi = lane & 3;
    extern __shared__ char smraw[];
    __nv_bfloat16* As = (__nv_bfloat16*)smraw;
    __nv_bfloat16* Bs = As + 128*136;
    const bool vmode = (yb == 2);

    {
        __nv_bfloat16* Xs = vmode ? Bs : As;
        const __nv_bfloat16* xn = g_xnt + ((size_t)b*HW + p0)*CH;
        for (int i = tid; i < 2048; i += 256) {
            const int r = i >> 4, c16 = i & 15;
            *(int4*)&Xs[r*136 + c16*8] = *(const int4*)&xn[(size_t)r*CH + c16*8];
        }
    }
    {
        __nv_bfloat16* Ws = vmode ? As : Bs;
        const float* Wt = W + (size_t)yb*128*CH;
        for (int i = tid; i < 4096; i += 256) {
            const int r = i >> 5, c4 = (i & 31)*4;
            float4 wv = *(const float4*)&Wt[(size_t)r*CH + c4];
            uint2 u;
            u.x = bf2bits(__floats2bfloat162_rn(wv.x, wv.y));
            u.y = bf2bits(__floats2bfloat162_rn(wv.z, wv.w));
            *(uint2*)&Ws[r*136 + c4] = u;
        }
    }
    __syncthreads();

    const uint32_t abase = smem_u32(As);
    const uint32_t bbase = smem_u32(Bs);

    uint32_t af[8][4];
    {
        const uint32_t arow = (uint32_t)(16*w + (lane & 7) + ((lane >> 3) & 1)*8);
        const uint32_t acoff = (uint32_t)((lane >> 4)*16);
#pragma unroll
        for (int kk = 0; kk < 8; kk++)
            ldsm4(af[kk][0], af[kk][1], af[kk][2], af[kk][3],
                  abase + arow*272 + kk*32 + acoff);
    }

    float cf[16][4];
#pragma unroll
    for (int j = 0; j < 16; j++)
#pragma unroll
        for (int r = 0; r < 4; r++) cf[j][r] = 0.f;

    const uint32_t browoff = (uint32_t)((((lane >> 4) & 1)*8 + (lane & 7))*272);
    const uint32_t bchoff  = (uint32_t)(((lane >> 3) & 1)*16);

#pragma unroll
    for (int kk = 0; kk < 8; kk++) {
#pragma unroll
        for (int jp = 0; jp < 8; jp++) {
            uint32_t r0, r1, r2, r3;
            ldsm4(r0, r1, r2, r3, bbase + jp*16*272 + browoff + kk*32 + bchoff);
            mma16816(cf[2*jp],   af[kk], r0, r1, cf[2*jp]);
            mma16816(cf[2*jp+1], af[kk], r2, r3, cf[2*jp+1]);
        }
    }

    if (!vmode) {
        const float sc = (yb == 0) ? SCALE_QL2E : 1.0f;
        __nv_bfloat16* dst = ((yb == 0) ? g_q : g_k) + (size_t)b*HW*CH;
        const int row0 = p0 + 16*w + g;
#pragma unroll
        for (int j = 0; j < 16; j++) {
            const int col = 8*j + 2*qi;
            const float b0 = __ldg(&bias[yb*128 + col]);
            const float b1 = __ldg(&bias[yb*128 + col + 1]);
            *(uint32_t*)&dst[(size_t)row0*CH + col] =
                bf2bits(__floats2bfloat162_rn((cf[j][0]+b0)*sc, (cf[j][1]+b1)*sc));
            *(uint32_t*)&dst[(size_t)(row0+8)*CH + col] =
                bf2bits(__floats2bfloat162_rn((cf[j][2]+b0)*sc, (cf[j][3]+b1)*sc));
        }
    } else {
        __nv_bfloat16* dst = g_v + (size_t)b*CH*HW;
        const int o = 16*w + g;
        const float b0 = __ldg(&bias[256 + o]);
        const float b1 = __ldg(&bias[256 + o + 8]);
#pragma unroll
        for (int j = 0; j < 16; j++) {
            const int p = p0 + 8*j + 2*qi;
            *(uint32_t*)&dst[(size_t)o*HW + p] =
                bf2bits(__floats2bfloat162_rn(cf[j][0]+b0, cf[j][1]+b0));
            *(uint32_t*)&dst[(size_t)(o+8)*HW + p] =
                bf2bits(__floats2bfloat162_rn(cf[j][2]+b1, cf[j][3]+b1));
        }
    }
}

// ============================ mma.sync flash attention (pipelined) ============================
#define TSTRIDE 136
#define TILE_B  (128*TSTRIDE*2)
#define OFF_Q   0
#define OFF_K0  (TILE_B)
#define OFF_K1  (2*TILE_B)
#define OFF_V0  (3*TILE_B)
#define OFF_V1  (4*TILE_B)
#define SM_FLASH (5*TILE_B)

__global__ void __launch_bounds__(256, 1) flash_mma_kernel() {
    extern __shared__ char smem[];
    const uint32_t sbase = smem_u32(smem);

    const int b    = blockIdx.y;
    const int n0   = blockIdx.x * 128;
    const int tid  = threadIdx.x;
    const int w    = tid >> 5;
    const int lane = tid & 31;
    const int g    = lane >> 2;
    const int qi   = lane & 3;

    const char* gq = (const char*)(g_q + (size_t)b*HW*CH);
    const char* gk = (const char*)(g_k + (size_t)b*HW*CH);
    const char* gv = (const char*)(g_v + (size_t)b*CH*HW);

    for (int i = 0; i < 8; i++) {
        const int idx = tid + i*256;
        const int r = idx >> 4, c16 = idx & 15;
        cpa16(sbase + OFF_Q + r*272 + c16*16, gq + (size_t)(n0 + r)*256 + c16*16);
    }
    CP_COMMIT();
    for (int i = 0; i < 8; i++) {
        const int idx = tid + i*256;
        const int r = idx >> 4, c16 = idx & 15;
        cpa16(sbase + OFF_K0 + r*272 + c16*16, gk + (size_t)r*256 + c16*16);
    }
    for (int i = 0; i < 8; i++) {
        const int idx = tid + i*256;
        const int r = idx >> 4, c16 = idx & 15;
        cpa16(sbase + OFF_V0 + r*272 + c16*16, gv + (size_t)r*(HW*2) + c16*16);
    }
    CP_COMMIT();
    CP_WAIT(1);
    __syncthreads();

    uint32_t qf[8][4];
    {
        const uint32_t qrow = (uint32_t)(16*w + (lane & 7) + ((lane >> 3) & 1)*8);
        const uint32_t qcoff = (uint32_t)((lane >> 4) * 16);
#pragma unroll
        for (int kk = 0; kk < 8; kk++)
            ldsm4(qf[kk][0], qf[kk][1], qf[kk][2], qf[kk][3],
                  sbase + OFF_Q + qrow*272 + kk*32 + qcoff);
    }

    float oa[16][4];
#pragma unroll
    for (int j = 0; j < 16; j++)
#pragma unroll
        for (int r = 0; r < 4; r++) oa[j][r] = 0.f;
    float rs0 = 0.f, rs1 = 0.f;

    const uint32_t browoff = (uint32_t)((((lane >> 4) & 1)*8 + (lane & 7))*272);
    const uint32_t bchoff  = (uint32_t)(((lane >> 3) & 1)*16);

    for (int kt = 0; kt < 32; kt++) {
        CP_WAIT(0);
        __syncthreads();

        if (kt < 31) {
            const int m1 = (kt + 1)*128;
            const uint32_t kb = sbase + (((kt + 1) & 1) ? OFF_K1 : OFF_K0);
            const uint32_t vb = sbase + (((kt + 1) & 1) ? OFF_V1 : OFF_V0);
            for (int i = 0; i < 8; i++) {
                const int idx = tid + i*256;
                const int r = idx >> 4, c16 = idx & 15;
                cpa16(kb + r*272 + c16*16, gk + (size_t)(m1 + r)*256 + c16*16);
            }
            for (int i = 0; i < 8; i++) {
                const int idx = tid + i*256;
                const int r = idx >> 4, c16 = idx & 15;
                cpa16(vb + r*272 + c16*16, gv + (size_t)r*(HW*2) + (size_t)m1*2 + c16*16);
            }
            CP_COMMIT();
        }

        const uint32_t kb = sbase + ((kt & 1) ? OFF_K1 : OFF_K0);
        const uint32_t vb = sbase + ((kt & 1) ? OFF_V1 : OFF_V0);

        // --- fine-grained pipeline over 16-key chunks j:
        //     S(j) -> PV(j-1) -> exp(j); PV(7) after the loop ---
        uint32_t pprev[4];
#pragma unroll
        for (int j = 0; j < 8; j++) {
            float sa[4] = {0.f, 0.f, 0.f, 0.f};
            float sb[4] = {0.f, 0.f, 0.f, 0.f};
#pragma unroll
            for (int kk = 0; kk < 8; kk++) {
                uint32_t r0, r1, r2, r3;
                ldsm4(r0, r1, r2, r3, kb + j*16*272 + browoff + kk*32 + bchoff);
                mma16816(sa, qf[kk], r0, r1, sa);
                mma16816(sb, qf[kk], r2, r3, sb);
            }
            if (j > 0) {
#pragma unroll
                for (int ch = 0; ch < 8; ch++) {
                    uint32_t r0, r1, r2, r3;
                    ldsm4(r0, r1, r2, r3, vb + ch*16*272 + browoff + (j-1)*32 + bchoff);
                    mma16816(oa[2*ch],   pprev, r0, r1, oa[2*ch]);
                    mma16816(oa[2*ch+1], pprev, r2, r3, oa[2*ch+1]);
                }
            }
            // exp via ex2 (log2e folded into Q scale)
            float ea0 = ex2f(sa[0]), ea1 = ex2f(sa[1]), ea2 = ex2f(sa[2]), ea3 = ex2f(sa[3]);
            float eb0 = ex2f(sb[0]), eb1 = ex2f(sb[1]), eb2 = ex2f(sb[2]), eb3 = ex2f(sb[3]);
            rs0 += ea0 + ea1 + eb0 + eb1;
            rs1 += ea2 + ea3 + eb2 + eb3;
            pprev[0] = bf2bits(__floats2bfloat162_rn(ea0, ea1));
            pprev[1] = bf2bits(__floats2bfloat162_rn(ea2, ea3));
            pprev[2] = bf2bits(__floats2bfloat162_rn(eb0, eb1));
            pprev[3] = bf2bits(__floats2bfloat162_rn(eb2, eb3));
        }
        // PV for the final chunk (j-1 == 7)
#pragma unroll
        for (int ch = 0; ch < 8; ch++) {
            uint32_t r0, r1, r2, r3;
            ldsm4(r0, r1, r2, r3, vb + ch*16*272 + browoff + 7*32 + bchoff);
            mma16816(oa[2*ch],   pprev, r0, r1, oa[2*ch]);
            mma16816(oa[2*ch+1], pprev, r2, r3, oa[2*ch+1]);
        }
    }

    rs0 += __shfl_xor_sync(0xffffffffu, rs0, 1);
    rs0 += __shfl_xor_sync(0xffffffffu, rs0, 2);
    rs1 += __shfl_xor_sync(0xffffffffu, rs1, 1);
    rs1 += __shfl_xor_sync(0xffffffffu, rs1, 2);
    const float inv0 = 1.0f / rs0;
    const float inv1 = 1.0f / rs1;

    __nv_bfloat16* ao = g_at + ((size_t)b*HW + n0)*CH;
    const int q0 = 16*w + g;
#pragma unroll
    for (int j = 0; j < 16; j++) {
        const int ch = 8*j + 2*qi;
        *(uint32_t*)&ao[(size_t)q0*CH + ch] =
            bf2bits(__floats2bfloat162_rn(oa[j][0]*inv0, oa[j][1]*inv0));
        *(uint32_t*)&ao[(size_t)(q0+8)*CH + ch] =
            bf2bits(__floats2bfloat162_rn(oa[j][2]*inv1, oa[j][3]*inv1));
    }
}

// ================== Output GEMM (mma.sync) + bias + residual ==================
__global__ void __launch_bounds__(256) out_mma_kernel(const float* __restrict__ W,
                                                      const float* __restrict__ bias,
                                                      const float* __restrict__ x,
                                                      float* __restrict__ out) {
    const int b  = blockIdx.y;
    const int p0 = blockIdx.x * 128;
    const int tid = threadIdx.x;
    const int w = tid >> 5, lane = tid & 31;
    const int g = lane >> 2, qi = lane & 3;
    extern __shared__ char smraw[];
    __nv_bfloat16* As = (__nv_bfloat16*)smraw;          // W [o][c]
    __nv_bfloat16* Bs = As + 128*136;                   // attn [p][c]

    for (int i = tid; i < 4096; i += 256) {
        const int r = i >> 5, c4 = (i & 31)*4;
        float4 wv = *(const float4*)&W[(size_t)r*CH + c4];
        uint2 u;
        u.x = bf2bits(__floats2bfloat162_rn(wv.x, wv.y));
        u.y = bf2bits(__floats2bfloat162_rn(wv.z, wv.w));
        *(uint2*)&As[r*136 + c4] = u;
    }
    const __nv_bfloat16* at = g_at + ((size_t)b*HW + p0)*CH;
    for (int i = tid; i < 2048; i += 256) {
        const int r = i >> 4, c16 = i & 15;
        *(int4*)&Bs[r*136 + c16*8] = *(const int4*)&at[(size_t)r*CH + c16*8];
    }
    __syncthreads();

    const uint32_t abase = smem_u32(As);
    const uint32_t bbase = smem_u32(Bs);

    uint32_t af[8][4];
    {
        const uint32_t arow = (uint32_t)(16*w + (lane & 7) + ((lane >> 3) & 1)*8);
        const uint32_t acoff = (uint32_t)((lane >> 4)*16);
#pragma unroll
        for (int kk = 0; kk < 8; kk++)
            ldsm4(af[kk][0], af[kk][1], af[kk][2], af[kk][3],
                  abase + arow*272 + kk*32 + acoff);
    }

    float cf[16][4];
#pragma unroll
    for (int j = 0; j < 16; j++)
#pragma unroll
        for (int r = 0; r < 4; r++) cf[j][r] = 0.f;

    const uint32_t browoff = (uint32_t)((((lane >> 4) & 1)*8 + (lane & 7))*272);
    const uint32_t bchoff  = (uint32_t)(((lane >> 3) & 1)*16);

#pragma unroll
    for (int kk = 0; kk < 8; kk++) {
#pragma unroll
        for (int jp = 0; jp < 8; jp++) {
            uint32_t r0, r1, r2, r3;
            ldsm4(r0, r1, r2, r3, bbase + jp*16*272 + browoff + kk*32 + bchoff);
            mma16816(cf[2*jp],   af[kk], r0, r1, cf[2*jp]);
            mma16816(cf[2*jp+1], af[kk], r2, r3, cf[2*jp+1]);
        }
    }

    const int o = 16*w + g;
    const float b0 = __ldg(&bias[o]);
    const float b1 = __ldg(&bias[o + 8]);
    const size_t row0 = ((size_t)b*CH + o)*HW + p0;
    const size_t row1 = ((size_t)b*CH + o + 8)*HW + p0;
#pragma unroll
    for (int j = 0; j < 16; j++) {
        const int p = 8*j + 2*qi;
        float2 x0 = *(const float2*)&x[row0 + p];
        float2 x1 = *(const float2*)&x[row1 + p];
        float2 v0; v0.x = cf[j][0] + b0 + x0.x; v0.y = cf[j][1] + b0 + x0.y;
        float2 v1; v1.x = cf[j][2] + b1 + x1.x; v1.y = cf[j][3] + b1 + x1.y;
        *(float2*)&out[row0 + p] = v0;
        *(float2*)&out[row1 + p] = v1;
    }
}

// ===================================================================
extern "C" void kernel_launch(void* const* d_in, const int* in_sizes, int n_in,
                              void* d_out, int out_size) {
    const float* x     = (const float*)d_in[0];
    const float* gamma = (const float*)d_in[1];
    const float* beta  = (const float*)d_in[2];
    const float* w_qkv = (const float*)d_in[3];
    const float* b_qkv = (const float*)d_in[4];
    const float* w_out = (const float*)d_in[5];
    const float* b_out = (const float*)d_in[6];
    float*       out   = (float*)d_out;

    cudaFuncSetAttribute(qkv_mma_kernel,  cudaFuncAttributeMaxDynamicSharedMemorySize, (int)SM_MMA);
    cudaFuncSetAttribute(flash_mma_kernel,cudaFuncAttributeMaxDynamicSharedMemorySize, (int)SM_FLASH);
    cudaFuncSetAttribute(out_mma_kernel,  cudaFuncAttributeMaxDynamicSharedMemorySize, (int)SM_MMA);

    gn_stats_kernel<<<BATCH*NG, 256>>>(x);

    dim3 ga(HW/128, BATCH);
    gn_apply_kernel<<<ga, 256>>>(x, gamma, beta);

    dim3 gq(HW/128, 3, BATCH);
    qkv_mma_kernel<<<gq, 256, SM_MMA>>>(w_qkv, b_qkv);

    dim3 gf(HW/128, BATCH);
    flash_mma_kernel<<<gf, 256, SM_FLASH>>>();

    dim3 go(HW/128, BATCH);
    out_mma_kernel<<<go, 256, SM_MMA>>>(w_out, b_out, x, out);
}

// round 12
// speedup vs baseline: 8.1748x; 1.0576x over previous
#include <cuda_runtime.h>
#include <cuda_bf16.h>
#include <cstdint>

#define BATCH 8
#define CH    128
#define HW    4096
#define NG    32
#define CPG   4
#define GRP_ELEMS (CPG*HW)
// 1/sqrt(128) * log2(e): softmax done with ex2 (e^S = 2^(S*log2e))
#define SCALE_QL2E (0.08838834764831845f * 1.4426950408889634f)

__device__ __nv_bfloat16 g_xnt [BATCH*HW*CH];   // [b][p][c] groupnormed, bf16
__device__ __nv_bfloat16 g_q   [BATCH*HW*CH];   // [b][n][c], scale*log2e folded
__device__ __nv_bfloat16 g_k   [BATCH*HW*CH];   // [b][m][c]
__device__ __nv_bfloat16 g_v   [BATCH*CH*HW];   // [b][c][m]
__device__ __nv_bfloat16 g_at  [BATCH*HW*CH];   // [b][n][c] attention out
__device__ float2        g_stats[BATCH*NG];     // mean, rstd per (b,g)

// ---------------- mma.sync / ldmatrix / cp.async helpers ----------------
__device__ __forceinline__ uint32_t smem_u32(const void* p) {
    uint32_t a;
    asm("{ .reg .u64 t; cvta.to.shared.u64 t, %1; cvt.u32.u64 %0, t; }" : "=r"(a) : "l"(p));
    return a;
}
__device__ __forceinline__ void ldsm4(uint32_t& r0, uint32_t& r1, uint32_t& r2, uint32_t& r3, uint32_t addr) {
    asm volatile("ldmatrix.sync.aligned.m8n8.x4.shared.b16 {%0,%1,%2,%3}, [%4];"
        : "=r"(r0), "=r"(r1), "=r"(r2), "=r"(r3) : "r"(addr));
}
__device__ __forceinline__ void mma16816(float* d, const uint32_t* a, uint32_t b0, uint32_t b1,
                                         const float* c) {
    asm volatile("mma.sync.aligned.m16n8k16.row.col.f32.bf16.bf16.f32 "
        "{%0,%1,%2,%3}, {%4,%5,%6,%7}, {%8,%9}, {%10,%11,%12,%13};"
        : "=f"(d[0]), "=f"(d[1]), "=f"(d[2]), "=f"(d[3])
        : "r"(a[0]), "r"(a[1]), "r"(a[2]), "r"(a[3]), "r"(b0), "r"(b1),
          "f"(c[0]), "f"(c[1]), "f"(c[2]), "f"(c[3]));
}
__device__ __forceinline__ void cpa16(uint32_t dst, const void* src) {
    asm volatile("cp.async.cg.shared.global [%0], [%1], 16;" :: "r"(dst), "l"(src));
}
#define CP_COMMIT() asm volatile("cp.async.commit_group;" ::: "memory")
#define CP_WAIT(n)  asm volatile("cp.async.wait_group %0;" :: "n"(n) : "memory")

__device__ __forceinline__ uint32_t bf2bits(__nv_bfloat162 v) { return *(const uint32_t*)&v; }
__device__ __forceinline__ float ex2f(float x) {
    float r; asm("ex2.approx.ftz.f32 %0, %1;" : "=f"(r) : "f"(x)); return r;
}

// ============================ GroupNorm stats ============================
__global__ void __launch_bounds__(256) gn_stats_kernel(const float* __restrict__ x) {
    const int bg  = blockIdx.x;
    const int tid = threadIdx.x;
    const float4* src4 = (const float4*)(x + (size_t)bg * GRP_ELEMS);

    float s = 0.f, ss = 0.f;
    for (int i = tid; i < GRP_ELEMS/4; i += 256) {
        float4 v = src4[i];
        s  += v.x + v.y + v.z + v.w;
        ss += v.x*v.x + v.y*v.y + v.z*v.z + v.w*v.w;
    }
    __shared__ float rs[256], rss[256];
    rs[tid] = s; rss[tid] = ss;
    __syncthreads();
    for (int o = 128; o > 0; o >>= 1) {
        if (tid < o) { rs[tid] += rs[tid+o]; rss[tid] += rss[tid+o]; }
        __syncthreads();
    }
    if (tid == 0) {
        const float mean = rs[0]  * (1.f/GRP_ELEMS);
        const float var  = rss[0] * (1.f/GRP_ELEMS) - mean*mean;
        g_stats[bg] = make_float2(mean, rsqrtf(var + 1e-5f));
    }
}

// ============================ GroupNorm apply + transpose -> bf16 [p][c] ============================
__global__ void __launch_bounds__(256) gn_apply_kernel(const float* __restrict__ x,
                                                       const float* __restrict__ gamma,
                                                       const float* __restrict__ beta) {
    const int b   = blockIdx.y;
    const int p0  = blockIdx.x * 128;
    const int tid = threadIdx.x;
    __shared__ __nv_bfloat16 Xs[128*136];
    __shared__ float scl[128], sft[128];

    if (tid < 128) {
        float2 st = g_stats[b*NG + (tid >> 2)];
        const float sc = st.y * gamma[tid];
        scl[tid] = sc;
        sft[tid] = beta[tid] - st.x * sc;
    }
    __syncthreads();

    const int p    = tid & 127;
    const int half = tid >> 7;
    const float* xb = x + (size_t)b*CH*HW + p0 + p;
#pragma unroll
    for (int cg = 0; cg < 16; cg++) {
        const int c = half*64 + cg*4;
        float v0 = xb[(size_t)(c+0)*HW]*scl[c+0] + sft[c+0];
        float v1 = xb[(size_t)(c+1)*HW]*scl[c+1] + sft[c+1];
        float v2 = xb[(size_t)(c+2)*HW]*scl[c+2] + sft[c+2];
        float v3 = xb[(size_t)(c+3)*HW]*scl[c+3] + sft[c+3];
        uint2 u;
        u.x = bf2bits(__floats2bfloat162_rn(v0, v1));
        u.y = bf2bits(__floats2bfloat162_rn(v2, v3));
        *(uint2*)&Xs[p*136 + c] = u;
    }
    __syncthreads();

    __nv_bfloat16* dst = g_xnt + ((size_t)b*HW + p0)*CH;
    for (int i = tid; i < 2048; i += 256) {
        const int pr = i >> 4, c16 = i & 15;
        *(int4*)&dst[(size_t)pr*CH + c16*8] = *(const int4*)&Xs[pr*136 + c16*8];
    }
}

// ============================ QKV GEMM (mma.sync bf16) ============================
#define SM_MMA (2*128*136*2)   // 69632 B

__global__ void __launch_bounds__(256) qkv_mma_kernel(const float* __restrict__ W,
                                                      const float* __restrict__ bias) {
    const int b  = blockIdx.z;
    const int yb = blockIdx.y;
    const int p0 = blockIdx.x * 128;
    const int tid = threadIdx.x;
    const int w = tid >> 5, lane = tid & 31;
    const int g = lane >> 2, qi = lane & 3;
    extern __shared__ char smraw[];
    __nv_bfloat16* As = (__nv_bfloat16*)smraw;
    __nv_bfloat16* Bs = As + 128*136;
    const bool vmode = (yb == 2);

    {
        __nv_bfloat16* Xs = vmode ? Bs : As;
        const __nv_bfloat16* xn = g_xnt + ((size_t)b*HW + p0)*CH;
        for (int i = tid; i < 2048; i += 256) {
            const int r = i >> 4, c16 = i & 15;
            *(int4*)&Xs[r*136 + c16*8] = *(const int4*)&xn[(size_t)r*CH + c16*8];
        }
    }
    {
        __nv_bfloat16* Ws = vmode ? As : Bs;
        const float* Wt = W + (size_t)yb*128*CH;
        for (int i = tid; i < 4096; i += 256) {
            const int r = i >> 5, c4 = (i & 31)*4;
            float4 wv = *(const float4*)&Wt[(size_t)r*CH + c4];
            uint2 u;
            u.x = bf2bits(__floats2bfloat162_rn(wv.x, wv.y));
            u.y = bf2bits(__floats2bfloat162_rn(wv.z, wv.w));
            *(uint2*)&Ws[r*136 + c4] = u;
        }
    }
    __syncthreads();

    const uint32_t abase = smem_u32(As);
    const uint32_t bbase = smem_u32(Bs);

    uint32_t af[8][4];
    {
        const uint32_t arow = (uint32_t)(16*w + (lane & 7) + ((lane >> 3) & 1)*8);
        const uint32_t acoff = (uint32_t)((lane >> 4)*16);
#pragma unroll
        for (int kk = 0; kk < 8; kk++)
            ldsm4(af[kk][0], af[kk][1], af[kk][2], af[kk][3],
                  abase + arow*272 + kk*32 + acoff);
    }

    float cf[16][4];
#pragma unroll
    for (int j = 0; j < 16; j++)
#pragma unroll
        for (int r = 0; r < 4; r++) cf[j][r] = 0.f;

    const uint32_t browoff = (uint32_t)((((lane >> 4) & 1)*8 + (lane & 7))*272);
    const uint32_t bchoff  = (uint32_t)(((lane >> 3) & 1)*16);

#pragma unroll
    for (int kk = 0; kk < 8; kk++) {
#pragma unroll
        for (int jp = 0; jp < 8; jp++) {
            uint32_t r0, r1, r2, r3;
            ldsm4(r0, r1, r2, r3, bbase + jp*16*272 + browoff + kk*32 + bchoff);
            mma16816(cf[2*jp],   af[kk], r0, r1, cf[2*jp]);
            mma16816(cf[2*jp+1], af[kk], r2, r3, cf[2*jp+1]);
        }
    }

    if (!vmode) {
        const float sc = (yb == 0) ? SCALE_QL2E : 1.0f;
        __nv_bfloat16* dst = ((yb == 0) ? g_q : g_k) + (size_t)b*HW*CH;
        const int row0 = p0 + 16*w + g;
#pragma unroll
        for (int j = 0; j < 16; j++) {
            const int col = 8*j + 2*qi;
            const float b0 = __ldg(&bias[yb*128 + col]);
            const float b1 = __ldg(&bias[yb*128 + col + 1]);
            *(uint32_t*)&dst[(size_t)row0*CH + col] =
                bf2bits(__floats2bfloat162_rn((cf[j][0]+b0)*sc, (cf[j][1]+b1)*sc));
            *(uint32_t*)&dst[(size_t)(row0+8)*CH + col] =
                bf2bits(__floats2bfloat162_rn((cf[j][2]+b0)*sc, (cf[j][3]+b1)*sc));
        }
    } else {
        __nv_bfloat16* dst = g_v + (size_t)b*CH*HW;
        const int o = 16*w + g;
        const float b0 = __ldg(&bias[256 + o]);
        const float b1 = __ldg(&bias[256 + o + 8]);
#pragma unroll
        for (int j = 0; j < 16; j++) {
            const int p = p0 + 8*j + 2*qi;
            *(uint32_t*)&dst[(size_t)o*HW + p] =
                bf2bits(__floats2bfloat162_rn(cf[j][0]+b0, cf[j][1]+b0));
            *(uint32_t*)&dst[(size_t)(o+8)*HW + p] =
                bf2bits(__floats2bfloat162_rn(cf[j][2]+b1, cf[j][3]+b1));
        }
    }
}

// ============================ mma.sync flash attention (512 thr, 256 queries/CTA) ============================
#define TSTRIDE 136
#define QTILE_B (256*TSTRIDE*2)          // 69632
#define KTILE_B (128*TSTRIDE*2)          // 34816
#define OFF_Q   0
#define OFF_K0  (QTILE_B)
#define OFF_K1  (QTILE_B + KTILE_B)
#define OFF_V0  (QTILE_B + 2*KTILE_B)
#define OFF_V1  (QTILE_B + 3*KTILE_B)
#define SM_FLASH (QTILE_B + 4*KTILE_B)   // 208896

__global__ void __launch_bounds__(512, 1) flash_mma_kernel() {
    extern __shared__ char smem[];
    const uint32_t sbase = smem_u32(smem);

    const int b    = blockIdx.y;
    const int n0   = blockIdx.x * 256;
    const int tid  = threadIdx.x;
    const int w    = tid >> 5;           // 0..15
    const int lane = tid & 31;
    const int g    = lane >> 2;
    const int qi   = lane & 3;

    const char* gq = (const char*)(g_q + (size_t)b*HW*CH);
    const char* gk = (const char*)(g_k + (size_t)b*HW*CH);
    const char* gv = (const char*)(g_v + (size_t)b*CH*HW);

    // prologue: Q (256 rows) + K0 + V0, one commit group
    for (int i = 0; i < 8; i++) {
        const int idx = tid + i*512;
        const int r = idx >> 4, c16 = idx & 15;
        cpa16(sbase + OFF_Q + r*272 + c16*16, gq + (size_t)(n0 + r)*256 + c16*16);
    }
    for (int i = 0; i < 4; i++) {
        const int idx = tid + i*512;
        const int r = idx >> 4, c16 = idx & 15;
        cpa16(sbase + OFF_K0 + r*272 + c16*16, gk + (size_t)r*256 + c16*16);
    }
    for (int i = 0; i < 4; i++) {
        const int idx = tid + i*512;
        const int r = idx >> 4, c16 = idx & 15;
        cpa16(sbase + OFF_V0 + r*272 + c16*16, gv + (size_t)r*(HW*2) + c16*16);
    }
    CP_COMMIT();

    float oa[16][4];
#pragma unroll
    for (int j = 0; j < 16; j++)
#pragma unroll
        for (int r = 0; r < 4; r++) oa[j][r] = 0.f;
    float rs0 = 0.f, rs1 = 0.f;

    const uint32_t qldoff = (uint32_t)(OFF_Q + (16*w + (lane & 7) + ((lane >> 3) & 1)*8)*272
                                       + (lane >> 4)*16);
    const uint32_t browoff = (uint32_t)((((lane >> 4) & 1)*8 + (lane & 7))*272);
    const uint32_t bchoff  = (uint32_t)(((lane >> 3) & 1)*16);

    for (int kt = 0; kt < 32; kt++) {
        CP_WAIT(0);
        __syncthreads();

        if (kt < 31) {
            const int m1 = (kt + 1)*128;
            const uint32_t kb2 = sbase + (((kt + 1) & 1) ? OFF_K1 : OFF_K0);
            const uint32_t vb2 = sbase + (((kt + 1) & 1) ? OFF_V1 : OFF_V0);
            for (int i = 0; i < 4; i++) {
                const int idx = tid + i*512;
                const int r = idx >> 4, c16 = idx & 15;
                cpa16(kb2 + r*272 + c16*16, gk + (size_t)(m1 + r)*256 + c16*16);
            }
            for (int i = 0; i < 4; i++) {
                const int idx = tid + i*512;
                const int r = idx >> 4, c16 = idx & 15;
                cpa16(vb2 + r*272 + c16*16, gv + (size_t)r*(HW*2) + (size_t)m1*2 + c16*16);
            }
            CP_COMMIT();
        }

        const uint32_t kb = sbase + ((kt & 1) ? OFF_K1 : OFF_K0);
        const uint32_t vb = sbase + ((kt & 1) ? OFF_V1 : OFF_V0);

        // Q frags reloaded per tile (register diet: not live across tiles)
        uint32_t qf[8][4];
#pragma unroll
        for (int kk = 0; kk < 8; kk++)
            ldsm4(qf[kk][0], qf[kk][1], qf[kk][2], qf[kk][3],
                  sbase + qldoff + kk*32);

        uint32_t pprev[4];
#pragma unroll
        for (int j = 0; j < 8; j++) {
            float sa[4] = {0.f, 0.f, 0.f, 0.f};
            float sb[4] = {0.f, 0.f, 0.f, 0.f};
#pragma unroll
            for (int kk = 0; kk < 8; kk++) {
                uint32_t r0, r1, r2, r3;
                ldsm4(r0, r1, r2, r3, kb + j*16*272 + browoff + kk*32 + bchoff);
                mma16816(sa, qf[kk], r0, r1, sa);
                mma16816(sb, qf[kk], r2, r3, sb);
            }
            if (j > 0) {
#pragma unroll
                for (int ch = 0; ch < 8; ch++) {
                    uint32_t r0, r1, r2, r3;
                    ldsm4(r0, r1, r2, r3, vb + ch*16*272 + browoff + (j-1)*32 + bchoff);
                    mma16816(oa[2*ch],   pprev, r0, r1, oa[2*ch]);
                    mma16816(oa[2*ch+1], pprev, r2, r3, oa[2*ch+1]);
                }
            }
            float ea0 = ex2f(sa[0]), ea1 = ex2f(sa[1]), ea2 = ex2f(sa[2]), ea3 = ex2f(sa[3]);
            float eb0 = ex2f(sb[0]), eb1 = ex2f(sb[1]), eb2 = ex2f(sb[2]), eb3 = ex2f(sb[3]);
            rs0 += ea0 + ea1 + eb0 + eb1;
            rs1 += ea2 + ea3 + eb2 + eb3;
            pprev[0] = bf2bits(__floats2bfloat162_rn(ea0, ea1));
            pprev[1] = bf2bits(__floats2bfloat162_rn(ea2, ea3));
            pprev[2] = bf2bits(__floats2bfloat162_rn(eb0, eb1));
            pprev[3] = bf2bits(__floats2bfloat162_rn(eb2, eb3));
        }
#pragma unroll
        for (int ch = 0; ch < 8; ch++) {
            uint32_t r0, r1, r2, r3;
            ldsm4(r0, r1, r2, r3, vb + ch*16*272 + browoff + 7*32 + bchoff);
            mma16816(oa[2*ch],   pprev, r0, r1, oa[2*ch]);
            mma16816(oa[2*ch+1], pprev, r2, r3, oa[2*ch+1]);
        }
    }

    rs0 += __shfl_xor_sync(0xffffffffu, rs0, 1);
    rs0 += __shfl_xor_sync(0xffffffffu, rs0, 2);
    rs1 += __shfl_xor_sync(0xffffffffu, rs1, 1);
    rs1 += __shfl_xor_sync(0xffffffffu, rs1, 2);
    const float inv0 = 1.0f / rs0;
    const float inv1 = 1.0f / rs1;

    __nv_bfloat16* ao = g_at + ((size_t)b*HW + n0)*CH;
    const int q0 = 16*w + g;
#pragma unroll
    for (int j = 0; j < 16; j++) {
        const int ch = 8*j + 2*qi;
        *(uint32_t*)&ao[(size_t)q0*CH + ch] =
            bf2bits(__floats2bfloat162_rn(oa[j][0]*inv0, oa[j][1]*inv0));
        *(uint32_t*)&ao[(size_t)(q0+8)*CH + ch] =
            bf2bits(__floats2bfloat162_rn(oa[j][2]*inv1, oa[j][3]*inv1));
    }
}

// ================== Output GEMM (mma.sync) + bias + residual ==================
__global__ void __launch_bounds__(256) out_mma_kernel(const float* __restrict__ W,
                                                      const float* __restrict__ bias,
                                                      const float* __restrict__ x,
                                                      float* __restrict__ out) {
    const int b  = blockIdx.y;
    const int p0 = blockIdx.x * 128;
    const int tid = threadIdx.x;
    const int w = tid >> 5, lane = tid & 31;
    const int g = lane >> 2, qi = lane & 3;
    extern __shared__ char smraw[];
    __nv_bfloat16* As = (__nv_bfloat16*)smraw;          // W [o][c]
    __nv_bfloat16* Bs = As + 128*136;                   // attn [p][c]

    for (int i = tid; i < 4096; i += 256) {
        const int r = i >> 5, c4 = (i & 31)*4;
        float4 wv = *(const float4*)&W[(size_t)r*CH + c4];
        uint2 u;
        u.x = bf2bits(__floats2bfloat162_rn(wv.x, wv.y));
        u.y = bf2bits(__floats2bfloat162_rn(wv.z, wv.w));
        *(uint2*)&As[r*136 + c4] = u;
    }
    const __nv_bfloat16* at = g_at + ((size_t)b*HW + p0)*CH;
    for (int i = tid; i < 2048; i += 256) {
        const int r = i >> 4, c16 = i & 15;
        *(int4*)&Bs[r*136 + c16*8] = *(const int4*)&at[(size_t)r*CH + c16*8];
    }
    __syncthreads();

    const uint32_t abase = smem_u32(As);
    const uint32_t bbase = smem_u32(Bs);

    uint32_t af[8][4];
    {
        const uint32_t arow = (uint32_t)(16*w + (lane & 7) + ((lane >> 3) & 1)*8);
        const uint32_t acoff = (uint32_t)((lane >> 4)*16);
#pragma unroll
        for (int kk = 0; kk < 8; kk++)
            ldsm4(af[kk][0], af[kk][1], af[kk][2], af[kk][3],
                  abase + arow*272 + kk*32 + acoff);
    }

    float cf[16][4];
#pragma unroll
    for (int j = 0; j < 16; j++)
#pragma unroll
        for (int r = 0; r < 4; r++) cf[j][r] = 0.f;

    const uint32_t browoff = (uint32_t)((((lane >> 4) & 1)*8 + (lane & 7))*272);
    const uint32_t bchoff  = (uint32_t)(((lane >> 3) & 1)*16);

#pragma unroll
    for (int kk = 0; kk < 8; kk++) {
#pragma unroll
        for (int jp = 0; jp < 8; jp++) {
            uint32_t r0, r1, r2, r3;
            ldsm4(r0, r1, r2, r3, bbase + jp*16*272 + browoff + kk*32 + bchoff);
            mma16816(cf[2*jp],   af[kk], r0, r1, cf[2*jp]);
            mma16816(cf[2*jp+1], af[kk], r2, r3, cf[2*jp+1]);
        }
    }

    const int o = 16*w + g;
    const float b0 = __ldg(&bias[o]);
    const float b1 = __ldg(&bias[o + 8]);
    const size_t row0 = ((size_t)b*CH + o)*HW + p0;
    const size_t row1 = ((size_t)b*CH + o + 8)*HW + p0;
#pragma unroll
    for (int j = 0; j < 16; j++) {
        const int p = 8*j + 2*qi;
        float2 x0 = *(const float2*)&x[row0 + p];
        float2 x1 = *(const float2*)&x[row1 + p];
        float2 v0; v0.x = cf[j][0] + b0 + x0.x; v0.y = cf[j][1] + b0 + x0.y;
        float2 v1; v1.x = cf[j][2] + b1 + x1.x; v1.y = cf[j][3] + b1 + x1.y;
        *(float2*)&out[row0 + p] = v0;
        *(float2*)&out[row1 + p] = v1;
    }
}

// ===================================================================
extern "C" void kernel_launch(void* const* d_in, const int* in_sizes, int n_in,
                              void* d_out, int out_size) {
    const float* x     = (const float*)d_in[0];
    const float* gamma = (const float*)d_in[1];
    const float* beta  = (const float*)d_in[2];
    const float* w_qkv = (const float*)d_in[3];
    const float* b_qkv = (const float*)d_in[4];
    const float* w_out = (const float*)d_in[5];
    const float* b_out = (const float*)d_in[6];
    float*       out   = (float*)d_out;

    cudaFuncSetAttribute(qkv_mma_kernel,  cudaFuncAttributeMaxDynamicSharedMemorySize, (int)SM_MMA);
    cudaFuncSetAttribute(flash_mma_kernel,cudaFuncAttributeMaxDynamicSharedMemorySize, (int)SM_FLASH);
    cudaFuncSetAttribute(out_mma_kernel,  cudaFuncAttributeMaxDynamicSharedMemorySize, (int)SM_MMA);

    gn_stats_kernel<<<BATCH*NG, 256>>>(x);

    dim3 ga(HW/128, BATCH);
    gn_apply_kernel<<<ga, 256>>>(x, gamma, beta);

    dim3 gq(HW/128, 3, BATCH);
    qkv_mma_kernel<<<gq, 256, SM_MMA>>>(w_qkv, b_qkv);

    dim3 gf(HW/256, BATCH);                       // 16 x 8 = 128 CTAs, single wave
    flash_mma_kernel<<<gf, 512, SM_FLASH>>>();

    dim3 go(HW/128, BATCH);
    out_mma_kernel<<<go, 256, SM_MMA>>>(w_out, b_out, x, out);
}

// round 13
// speedup vs baseline: 8.2300x; 1.0068x over previous
#include <cuda_runtime.h>
#include <cuda_bf16.h>
#include <cstdint>

#define BATCH 8
#define CH    128
#define HW    4096
#define NG    32
#define CPG   4
#define GRP_ELEMS (CPG*HW)
// 1/sqrt(128) * log2(e): softmax done with ex2 (e^S = 2^(S*log2e))
#define SCALE_QL2E (0.08838834764831845f * 1.4426950408889634f)

__device__ __nv_bfloat16 g_xnt [BATCH*HW*CH];   // [b][p][c] groupnormed, bf16
__device__ __nv_bfloat16 g_q   [BATCH*HW*CH];   // [b][n][c], scale*log2e folded
__device__ __nv_bfloat16 g_k   [BATCH*HW*CH];   // [b][m][c]
__device__ __nv_bfloat16 g_v   [BATCH*CH*HW];   // [b][c][m]
__device__ __nv_bfloat16 g_at  [BATCH*HW*CH];   // [b][n][c] attention out
__device__ float2        g_stats[BATCH*NG];     // mean, rstd per (b,g)

// ---------------- mma.sync / ldmatrix / cp.async helpers ----------------
__device__ __forceinline__ uint32_t smem_u32(const void* p) {
    uint32_t a;
    asm("{ .reg .u64 t; cvta.to.shared.u64 t, %1; cvt.u32.u64 %0, t; }" : "=r"(a) : "l"(p));
    return a;
}
__device__ __forceinline__ void ldsm4(uint32_t& r0, uint32_t& r1, uint32_t& r2, uint32_t& r3, uint32_t addr) {
    asm volatile("ldmatrix.sync.aligned.m8n8.x4.shared.b16 {%0,%1,%2,%3}, [%4];"
        : "=r"(r0), "=r"(r1), "=r"(r2), "=r"(r3) : "r"(addr));
}
__device__ __forceinline__ void mma16816(float* d, const uint32_t* a, uint32_t b0, uint32_t b1,
                                         const float* c) {
    asm volatile("mma.sync.aligned.m16n8k16.row.col.f32.bf16.bf16.f32 "
        "{%0,%1,%2,%3}, {%4,%5,%6,%7}, {%8,%9}, {%10,%11,%12,%13};"
        : "=f"(d[0]), "=f"(d[1]), "=f"(d[2]), "=f"(d[3])
        : "r"(a[0]), "r"(a[1]), "r"(a[2]), "r"(a[3]), "r"(b0), "r"(b1),
          "f"(c[0]), "f"(c[1]), "f"(c[2]), "f"(c[3]));
}
__device__ __forceinline__ void cpa16(uint32_t dst, const void* src) {
    asm volatile("cp.async.cg.shared.global [%0], [%1], 16;" :: "r"(dst), "l"(src));
}
#define CP_COMMIT() asm volatile("cp.async.commit_group;" ::: "memory")
#define CP_WAIT(n)  asm volatile("cp.async.wait_group %0;" :: "n"(n) : "memory")

__device__ __forceinline__ uint32_t bf2bits(__nv_bfloat162 v) { return *(const uint32_t*)&v; }
__device__ __forceinline__ float ex2f(float x) {
    float r; asm("ex2.approx.ftz.f32 %0, %1;" : "=f"(r) : "f"(x)); return r;
}

// ============================ GroupNorm stats ============================
__global__ void __launch_bounds__(256) gn_stats_kernel(const float* __restrict__ x) {
    const int bg  = blockIdx.x;
    const int tid = threadIdx.x;
    const float4* src4 = (const float4*)(x + (size_t)bg * GRP_ELEMS);

    float s = 0.f, ss = 0.f;
    for (int i = tid; i < GRP_ELEMS/4; i += 256) {
        float4 v = src4[i];
        s  += v.x + v.y + v.z + v.w;
        ss += v.x*v.x + v.y*v.y + v.z*v.z + v.w*v.w;
    }
    __shared__ float rs[256], rss[256];
    rs[tid] = s; rss[tid] = ss;
    __syncthreads();
    for (int o = 128; o > 0; o >>= 1) {
        if (tid < o) { rs[tid] += rs[tid+o]; rss[tid] += rss[tid+o]; }
        __syncthreads();
    }
    if (tid == 0) {
        const float mean = rs[0]  * (1.f/GRP_ELEMS);
        const float var  = rss[0] * (1.f/GRP_ELEMS) - mean*mean;
        g_stats[bg] = make_float2(mean, rsqrtf(var + 1e-5f));
    }
}

// ============================ GroupNorm apply + transpose -> bf16 [p][c] ============================
__global__ void __launch_bounds__(256) gn_apply_kernel(const float* __restrict__ x,
                                                       const float* __restrict__ gamma,
                                                       const float* __restrict__ beta) {
    const int b   = blockIdx.y;
    const int p0  = blockIdx.x * 128;
    const int tid = threadIdx.x;
    __shared__ __nv_bfloat16 Xs[128*136];
    __shared__ float scl[128], sft[128];

    if (tid < 128) {
        float2 st = g_stats[b*NG + (tid >> 2)];
        const float sc = st.y * gamma[tid];
        scl[tid] = sc;
        sft[tid] = beta[tid] - st.x * sc;
    }
    __syncthreads();

    const int p    = tid & 127;
    const int half = tid >> 7;
    const float* xb = x + (size_t)b*CH*HW + p0 + p;
#pragma unroll
    for (int cg = 0; cg < 16; cg++) {
        const int c = half*64 + cg*4;
        float v0 = xb[(size_t)(c+0)*HW]*scl[c+0] + sft[c+0];
        float v1 = xb[(size_t)(c+1)*HW]*scl[c+1] + sft[c+1];
        float v2 = xb[(size_t)(c+2)*HW]*scl[c+2] + sft[c+2];
        float v3 = xb[(size_t)(c+3)*HW]*scl[c+3] + sft[c+3];
        uint2 u;
        u.x = bf2bits(__floats2bfloat162_rn(v0, v1));
        u.y = bf2bits(__floats2bfloat162_rn(v2, v3));
        *(uint2*)&Xs[p*136 + c] = u;
    }
    __syncthreads();

    __nv_bfloat16* dst = g_xnt + ((size_t)b*HW + p0)*CH;
    for (int i = tid; i < 2048; i += 256) {
        const int pr = i >> 4, c16 = i & 15;
        *(int4*)&dst[(size_t)pr*CH + c16*8] = *(const int4*)&Xs[pr*136 + c16*8];
    }
}

// ============================ QKV GEMM (mma.sync bf16) ============================
#define SM_MMA (2*128*136*2)   // 69632 B

__global__ void __launch_bounds__(256) qkv_mma_kernel(const float* __restrict__ W,
                                                      const float* __restrict__ bias) {
    const int b  = blockIdx.z;
    const int yb = blockIdx.y;
    const int p0 = blockIdx.x * 128;
    const int tid = threadIdx.x;
    const int w = tid >> 5, lane = tid & 31;
    const int g = lane >> 2, qi = lane & 3;
    extern __shared__ char smraw[];
    __nv_bfloat16* As = (__nv_bfloat16*)smraw;
    __nv_bfloat16* Bs = As + 128*136;
    const bool vmode = (yb == 2);

    {
        __nv_bfloat16* Xs = vmode ? Bs : As;
        const __nv_bfloat16* xn = g_xnt + ((size_t)b*HW + p0)*CH;
        for (int i = tid; i < 2048; i += 256) {
            const int r = i >> 4, c16 = i & 15;
            *(int4*)&Xs[r*136 + c16*8] = *(const int4*)&xn[(size_t)r*CH + c16*8];
        }
    }
    {
        __nv_bfloat16* Ws = vmode ? As : Bs;
        const float* Wt = W + (size_t)yb*128*CH;
        for (int i = tid; i < 4096; i += 256) {
            const int r = i >> 5, c4 = (i & 31)*4;
            float4 wv = *(const float4*)&Wt[(size_t)r*CH + c4];
            uint2 u;
            u.x = bf2bits(__floats2bfloat162_rn(wv.x, wv.y));
            u.y = bf2bits(__floats2bfloat162_rn(wv.z, wv.w));
            *(uint2*)&Ws[r*136 + c4] = u;
        }
    }
    __syncthreads();

    const uint32_t abase = smem_u32(As);
    const uint32_t bbase = smem_u32(Bs);

    uint32_t af[8][4];
    {
        const uint32_t arow = (uint32_t)(16*w + (lane & 7) + ((lane >> 3) & 1)*8);
        const uint32_t acoff = (uint32_t)((lane >> 4)*16);
#pragma unroll
        for (int kk = 0; kk < 8; kk++)
            ldsm4(af[kk][0], af[kk][1], af[kk][2], af[kk][3],
                  abase + arow*272 + kk*32 + acoff);
    }

    float cf[16][4];
#pragma unroll
    for (int j = 0; j < 16; j++)
#pragma unroll
        for (int r = 0; r < 4; r++) cf[j][r] = 0.f;

    const uint32_t browoff = (uint32_t)((((lane >> 4) & 1)*8 + (lane & 7))*272);
    const uint32_t bchoff  = (uint32_t)(((lane >> 3) & 1)*16);

#pragma unroll
    for (int kk = 0; kk < 8; kk++) {
#pragma unroll
        for (int jp = 0; jp < 8; jp++) {
            uint32_t r0, r1, r2, r3;
            ldsm4(r0, r1, r2, r3, bbase + jp*16*272 + browoff + kk*32 + bchoff);
            mma16816(cf[2*jp],   af[kk], r0, r1, cf[2*jp]);
            mma16816(cf[2*jp+1], af[kk], r2, r3, cf[2*jp+1]);
        }
    }

    if (!vmode) {
        const float sc = (yb == 0) ? SCALE_QL2E : 1.0f;
        __nv_bfloat16* dst = ((yb == 0) ? g_q : g_k) + (size_t)b*HW*CH;
        const int row0 = p0 + 16*w + g;
#pragma unroll
        for (int j = 0; j < 16; j++) {
            const int col = 8*j + 2*qi;
            const float b0 = __ldg(&bias[yb*128 + col]);
            const float b1 = __ldg(&bias[yb*128 + col + 1]);
            *(uint32_t*)&dst[(size_t)row0*CH + col] =
                bf2bits(__floats2bfloat162_rn((cf[j][0]+b0)*sc, (cf[j][1]+b1)*sc));
            *(uint32_t*)&dst[(size_t)(row0+8)*CH + col] =
                bf2bits(__floats2bfloat162_rn((cf[j][2]+b0)*sc, (cf[j][3]+b1)*sc));
        }
    } else {
        __nv_bfloat16* dst = g_v + (size_t)b*CH*HW;
        const int o = 16*w + g;
        const float b0 = __ldg(&bias[256 + o]);
        const float b1 = __ldg(&bias[256 + o + 8]);
#pragma unroll
        for (int j = 0; j < 16; j++) {
            const int p = p0 + 8*j + 2*qi;
            *(uint32_t*)&dst[(size_t)o*HW + p] =
                bf2bits(__floats2bfloat162_rn(cf[j][0]+b0, cf[j][1]+b0));
            *(uint32_t*)&dst[(size_t)(o+8)*HW + p] =
                bf2bits(__floats2bfloat162_rn(cf[j][2]+b1, cf[j][3]+b1));
        }
    }
}

// ============ mma.sync flash attention: 256 thr, 128 q/CTA, 2 CTAs/SM, 3-buffer ============
#define TSTRIDE 136
#define KTILE_B (128*TSTRIDE*2)          // 34816
#define SM_FLASH (3*KTILE_B)             // 104448 -> 2 CTAs/SM

__global__ void __launch_bounds__(256, 2) flash_mma_kernel() {
    extern __shared__ char smem[];
    const uint32_t sbase = smem_u32(smem);

    const int b    = blockIdx.y;
    const int n0   = blockIdx.x * 128;
    const int tid  = threadIdx.x;
    const int w    = tid >> 5;           // 0..7
    const int lane = tid & 31;
    const int g    = lane >> 2;
    const int qi   = lane & 3;

    const char* gq = (const char*)(g_q + (size_t)b*HW*CH);
    const char* gk = (const char*)(g_k + (size_t)b*HW*CH);
    const char* gv = (const char*)(g_v + (size_t)b*CH*HW);

    const uint32_t buf0 = sbase;
    const uint32_t buf1 = sbase + KTILE_B;
    const uint32_t buf2 = sbase + 2*KTILE_B;

    // prologue: Q -> buf0 (staging), K0 -> buf1, each its own group
    for (int i = 0; i < 8; i++) {
        const int idx = tid + i*256;
        const int r = idx >> 4, c16 = idx & 15;
        cpa16(buf0 + r*272 + c16*16, gq + (size_t)(n0 + r)*256 + c16*16);
    }
    CP_COMMIT();
    for (int i = 0; i < 8; i++) {
        const int idx = tid + i*256;
        const int r = idx >> 4, c16 = idx & 15;
        cpa16(buf1 + r*272 + c16*16, gk + (size_t)r*256 + c16*16);
    }
    CP_COMMIT();
    CP_WAIT(1);                 // Q done (oldest group)
    __syncthreads();

    // Q fragments persist in registers (no smem home afterwards)
    uint32_t qf[8][4];
    {
        const uint32_t qldoff = (uint32_t)((16*w + (lane & 7) + ((lane >> 3) & 1)*8)*272
                                           + (lane >> 4)*16);
#pragma unroll
        for (int kk = 0; kk < 8; kk++)
            ldsm4(qf[kk][0], qf[kk][1], qf[kk][2], qf[kk][3], buf0 + qldoff + kk*32);
    }
    __syncthreads();            // all warps done reading buf0

    // V0 -> buf2
    for (int i = 0; i < 8; i++) {
        const int idx = tid + i*256;
        const int r = idx >> 4, c16 = idx & 15;
        cpa16(buf2 + r*272 + c16*16, gv + (size_t)r*(HW*2) + c16*16);
    }
    CP_COMMIT();

    uint32_t bK = buf1, bV = buf2, bF = buf0;

    float oa[16][4];
#pragma unroll
    for (int j = 0; j < 16; j++)
#pragma unroll
        for (int r = 0; r < 4; r++) oa[j][r] = 0.f;
    float rs0 = 0.f, rs1 = 0.f;

    const uint32_t browoff = (uint32_t)((((lane >> 4) & 1)*8 + (lane & 7))*272);
    const uint32_t bchoff  = (uint32_t)(((lane >> 3) & 1)*16);

#pragma unroll 1
    for (int kt = 0; kt < 32; kt++) {
        CP_WAIT(1);             // K(kt) complete (older group); V(kt) may still fly
        __syncthreads();

        // ---- S(0) + exp(0) (V not needed yet) ----
        uint32_t pprev[4];
        {
            float sa[4] = {0.f,0.f,0.f,0.f};
            float sb[4] = {0.f,0.f,0.f,0.f};
#pragma unroll
            for (int kk = 0; kk < 8; kk++) {
                uint32_t r0, r1, r2, r3;
                ldsm4(r0, r1, r2, r3, bK + browoff + kk*32 + bchoff);
                mma16816(sa, qf[kk], r0, r1, sa);
                mma16816(sb, qf[kk], r2, r3, sb);
            }
            float ea0 = ex2f(sa[0]), ea1 = ex2f(sa[1]), ea2 = ex2f(sa[2]), ea3 = ex2f(sa[3]);
            float eb0 = ex2f(sb[0]), eb1 = ex2f(sb[1]), eb2 = ex2f(sb[2]), eb3 = ex2f(sb[3]);
            rs0 += ea0 + ea1 + eb0 + eb1;
            rs1 += ea2 + ea3 + eb2 + eb3;
            pprev[0] = bf2bits(__floats2bfloat162_rn(ea0, ea1));
            pprev[1] = bf2bits(__floats2bfloat162_rn(ea2, ea3));
            pprev[2] = bf2bits(__floats2bfloat162_rn(eb0, eb1));
            pprev[3] = bf2bits(__floats2bfloat162_rn(eb2, eb3));
        }

        CP_WAIT(0);             // V(kt) complete
        __syncthreads();

        // prefetch K(kt+1) into the free buffer (dead since last tile's top sync)
        if (kt < 31) {
            const int m1 = (kt + 1)*128;
            for (int i = 0; i < 8; i++) {
                const int idx = tid + i*256;
                const int r = idx >> 4, c16 = idx & 15;
                cpa16(bF + r*272 + c16*16, gk + (size_t)(m1 + r)*256 + c16*16);
            }
            CP_COMMIT();
        }

        // ---- pipelined j=1..7: S(j), PV(j-1), exp(j) ----
#pragma unroll
        for (int j = 1; j < 8; j++) {
            float sa[4] = {0.f,0.f,0.f,0.f};
            float sb[4] = {0.f,0.f,0.f,0.f};
#pragma unroll
            for (int kk = 0; kk < 8; kk++) {
                uint32_t r0, r1, r2, r3;
                ldsm4(r0, r1, r2, r3, bK + j*16*272 + browoff + kk*32 + bchoff);
                mma16816(sa, qf[kk], r0, r1, sa);
                mma16816(sb, qf[kk], r2, r3, sb);
            }
#pragma unroll
            for (int ch = 0; ch < 8; ch++) {
                uint32_t r0, r1, r2, r3;
                ldsm4(r0, r1, r2, r3, bV + ch*16*272 + browoff + (j-1)*32 + bchoff);
                mma16816(oa[2*ch],   pprev, r0, r1, oa[2*ch]);
                mma16816(oa[2*ch+1], pprev, r2, r3, oa[2*ch+1]);
            }
            float ea0 = ex2f(sa[0]), ea1 = ex2f(sa[1]), ea2 = ex2f(sa[2]), ea3 = ex2f(sa[3]);
            float eb0 = ex2f(sb[0]), eb1 = ex2f(sb[1]), eb2 = ex2f(sb[2]), eb3 = ex2f(sb[3]);
            rs0 += ea0 + ea1 + eb0 + eb1;
            rs1 += ea2 + ea3 + eb2 + eb3;
            pprev[0] = bf2bits(__floats2bfloat162_rn(ea0, ea1));
            pprev[1] = bf2bits(__floats2bfloat162_rn(ea2, ea3));
            pprev[2] = bf2bits(__floats2bfloat162_rn(eb0, eb1));
            pprev[3] = bf2bits(__floats2bfloat162_rn(eb2, eb3));
        }

        __syncthreads();        // all warps done reading bK (S(7) complete)

        // prefetch V(kt+1) into the dead K buffer
        if (kt < 31) {
            const int m1 = (kt + 1)*128;
            for (int i = 0; i < 8; i++) {
                const int idx = tid + i*256;
                const int r = idx >> 4, c16 = idx & 15;
                cpa16(bK + r*272 + c16*16, gv + (size_t)r*(HW*2) + (size_t)m1*2 + c16*16);
            }
            CP_COMMIT();
        }

        // PV(7)
#pragma unroll
        for (int ch = 0; ch < 8; ch++) {
            uint32_t r0, r1, r2, r3;
            ldsm4(r0, r1, r2, r3, bV + ch*16*272 + browoff + 7*32 + bchoff);
            mma16816(oa[2*ch],   pprev, r0, r1, oa[2*ch]);
            mma16816(oa[2*ch+1], pprev, r2, r3, oa[2*ch+1]);
        }

        // rotate: K' = prefetched K, V' = buffer now receiving V(kt+1), F' = dead V
        const uint32_t t = bK;
        bK = bF;
        bF = bV;
        bV = t;
    }

    rs0 += __shfl_xor_sync(0xffffffffu, rs0, 1);
    rs0 += __shfl_xor_sync(0xffffffffu, rs0, 2);
    rs1 += __shfl_xor_sync(0xffffffffu, rs1, 1);
    rs1 += __shfl_xor_sync(0xffffffffu, rs1, 2);
    const float inv0 = 1.0f / rs0;
    const float inv1 = 1.0f / rs1;

    __nv_bfloat16* ao = g_at + ((size_t)b*HW + n0)*CH;
    const int q0 = 16*w + g;
#pragma unroll
    for (int j = 0; j < 16; j++) {
        const int ch = 8*j + 2*qi;
        *(uint32_t*)&ao[(size_t)q0*CH + ch] =
            bf2bits(__floats2bfloat162_rn(oa[j][0]*inv0, oa[j][1]*inv0));
        *(uint32_t*)&ao[(size_t)(q0+8)*CH + ch] =
            bf2bits(__floats2bfloat162_rn(oa[j][2]*inv1, oa[j][3]*inv1));
    }
}

// ================== Output GEMM (mma.sync) + bias + residual ==================
__global__ void __launch_bounds__(256) out_mma_kernel(const float* __restrict__ W,
                                                      const float* __restrict__ bias,
                                                      const float* __restrict__ x,
                                                      float* __restrict__ out) {
    const int b  = blockIdx.y;
    const int p0 = blockIdx.x * 128;
    const int tid = threadIdx.x;
    const int w = tid >> 5, lane = tid & 31;
    const int g = lane >> 2, qi = lane & 3;
    extern __shared__ char smraw[];
    __nv_bfloat16* As = (__nv_bfloat16*)smraw;          // W [o][c]
    __nv_bfloat16* Bs = As + 128*136;                   // attn [p][c]

    for (int i = tid; i < 4096; i += 256) {
        const int r = i >> 5, c4 = (i & 31)*4;
        float4 wv = *(const float4*)&W[(size_t)r*CH + c4];
        uint2 u;
        u.x = bf2bits(__floats2bfloat162_rn(wv.x, wv.y));
        u.y = bf2bits(__floats2bfloat162_rn(wv.z, wv.w));
        *(uint2*)&As[r*136 + c4] = u;
    }
    const __nv_bfloat16* at = g_at + ((size_t)b*HW + p0)*CH;
    for (int i = tid; i < 2048; i += 256) {
        const int r = i >> 4, c16 = i & 15;
        *(int4*)&Bs[r*136 + c16*8] = *(const int4*)&at[(size_t)r*CH + c16*8];
    }
    __syncthreads();

    const uint32_t abase = smem_u32(As);
    const uint32_t bbase = smem_u32(Bs);

    uint32_t af[8][4];
    {
        const uint32_t arow = (uint32_t)(16*w + (lane & 7) + ((lane >> 3) & 1)*8);
        const uint32_t acoff = (uint32_t)((lane >> 4)*16);
#pragma unroll
        for (int kk = 0; kk < 8; kk++)
            ldsm4(af[kk][0], af[kk][1], af[kk][2], af[kk][3],
                  abase + arow*272 + kk*32 + acoff);
    }

    float cf[16][4];
#pragma unroll
    for (int j = 0; j < 16; j++)
#pragma unroll
        for (int r = 0; r < 4; r++) cf[j][r] = 0.f;

    const uint32_t browoff = (uint32_t)((((lane >> 4) & 1)*8 + (lane & 7))*272);
    const uint32_t bchoff  = (uint32_t)(((lane >> 3) & 1)*16);

#pragma unroll
    for (int kk = 0; kk < 8; kk++) {
#pragma unroll
        for (int jp = 0; jp < 8; jp++) {
            uint32_t r0, r1, r2, r3;
            ldsm4(r0, r1, r2, r3, bbase + jp*16*272 + browoff + kk*32 + bchoff);
            mma16816(cf[2*jp],   af[kk], r0, r1, cf[2*jp]);
            mma16816(cf[2*jp+1], af[kk], r2, r3, cf[2*jp+1]);
        }
    }

    const int o = 16*w + g;
    const float b0 = __ldg(&bias[o]);
    const float b1 = __ldg(&bias[o + 8]);
    const size_t row0 = ((size_t)b*CH + o)*HW + p0;
    const size_t row1 = ((size_t)b*CH + o + 8)*HW + p0;
#pragma unroll
    for (int j = 0; j < 16; j++) {
        const int p = 8*j + 2*qi;
        float2 x0 = *(const float2*)&x[row0 + p];
        float2 x1 = *(const float2*)&x[row1 + p];
        float2 v0; v0.x = cf[j][0] + b0 + x0.x; v0.y = cf[j][1] + b0 + x0.y;
        float2 v1; v1.x = cf[j][2] + b1 + x1.x; v1.y = cf[j][3] + b1 + x1.y;
        *(float2*)&out[row0 + p] = v0;
        *(float2*)&out[row1 + p] = v1;
    }
}

// ===================================================================
extern "C" void kernel_launch(void* const* d_in, const int* in_sizes, int n_in,
                              void* d_out, int out_size) {
    const float* x     = (const float*)d_in[0];
    const float* gamma = (const float*)d_in[1];
    const float* beta  = (const float*)d_in[2];
    const float* w_qkv = (const float*)d_in[3];
    const float* b_qkv = (const float*)d_in[4];
    const float* w_out = (const float*)d_in[5];
    const float* b_out = (const float*)d_in[6];
    float*       out   = (float*)d_out;

    cudaFuncSetAttribute(qkv_mma_kernel,  cudaFuncAttributeMaxDynamicSharedMemorySize, (int)SM_MMA);
    cudaFuncSetAttribute(flash_mma_kernel,cudaFuncAttributeMaxDynamicSharedMemorySize, (int)SM_FLASH);
    cudaFuncSetAttribute(out_mma_kernel,  cudaFuncAttributeMaxDynamicSharedMemorySize, (int)SM_MMA);

    gn_stats_kernel<<<BATCH*NG, 256>>>(x);

    dim3 ga(HW/128, BATCH);
    gn_apply_kernel<<<ga, 256>>>(x, gamma, beta);

    dim3 gq(HW/128, 3, BATCH);
    qkv_mma_kernel<<<gq, 256, SM_MMA>>>(w_qkv, b_qkv);

    dim3 gf(HW/128, BATCH);                       // 32 x 8 = 256 CTAs, 2 per SM
    flash_mma_kernel<<<gf, 256, SM_FLASH>>>();

    dim3 go(HW/128, BATCH);
    out_mma_kernel<<<go, 256, SM_MMA>>>(w_out, b_out, x, out);
}